// round 1
// baseline (speedup 1.0000x reference)
#include <cuda_runtime.h>
#include <math.h>

#define BB 2
#define LL 2048
#define DD 1024
#define HH 16
#define DH 64
#define ML (BB*LL)          // 4096 rows

// Scratch (allocation-free rule: device globals)
__device__ float g_qkv[ML * 3 * DD];   // [b,l,3,h,dh]
__device__ float g_att[ML * DD];       // [b,l,h,dh]

// ---------------------------------------------------------------------------
// Generic tiled GEMM: C[M,N] = A[M,K] @ W[N,K]^T   (both K-major, fp32)
// BM=BN=64, BK=16, 256 threads, 4x4 microtile per thread.
// ---------------------------------------------------------------------------
__global__ __launch_bounds__(256) void gemm_abt_kernel(
    const float* __restrict__ A, const float* __restrict__ W, float* __restrict__ C,
    int M, int N, int K)
{
    __shared__ float As[16][64];  // [k][m]
    __shared__ float Ws[16][64];  // [k][n]

    const int tid = threadIdx.x;
    const int tx = tid & 15;          // n group
    const int ty = tid >> 4;          // m group
    const int m0 = blockIdx.y * 64;
    const int n0 = blockIdx.x * 64;

    const int lr  = tid >> 2;         // 0..63 row within tile
    const int lk  = (tid & 3) * 4;    // 0,4,8,12 k offset

    float acc[4][4];
#pragma unroll
    for (int i = 0; i < 4; i++)
#pragma unroll
        for (int j = 0; j < 4; j++) acc[i][j] = 0.f;

    for (int kt = 0; kt < K; kt += 16) {
        // load A tile (64 rows x 16 k), transpose into As[k][m]
        float4 av = *reinterpret_cast<const float4*>(&A[(size_t)(m0 + lr) * K + kt + lk]);
        float4 wv = *reinterpret_cast<const float4*>(&W[(size_t)(n0 + lr) * K + kt + lk]);
        As[lk + 0][lr] = av.x; As[lk + 1][lr] = av.y; As[lk + 2][lr] = av.z; As[lk + 3][lr] = av.w;
        Ws[lk + 0][lr] = wv.x; Ws[lk + 1][lr] = wv.y; Ws[lk + 2][lr] = wv.z; Ws[lk + 3][lr] = wv.w;
        __syncthreads();

#pragma unroll
        for (int k = 0; k < 16; k++) {
            float4 a = *reinterpret_cast<const float4*>(&As[k][ty * 4]);
            float4 w = *reinterpret_cast<const float4*>(&Ws[k][tx * 4]);
            float am[4] = {a.x, a.y, a.z, a.w};
            float wn[4] = {w.x, w.y, w.z, w.w};
#pragma unroll
            for (int i = 0; i < 4; i++)
#pragma unroll
                for (int j = 0; j < 4; j++) acc[i][j] = fmaf(am[i], wn[j], acc[i][j]);
        }
        __syncthreads();
    }

#pragma unroll
    for (int i = 0; i < 4; i++) {
        float4 v = make_float4(acc[i][0], acc[i][1], acc[i][2], acc[i][3]);
        *reinterpret_cast<float4*>(&C[(size_t)(m0 + ty * 4 + i) * N + n0 + tx * 4]) = v;
    }
}

// ---------------------------------------------------------------------------
// RoPE in-place on q (sel 0) and k (sel 1) parts of g_qkv.
// one thread per (b,l,h,i) with i in [0,32): handles the (i, i+32) pair.
// ---------------------------------------------------------------------------
__global__ __launch_bounds__(256) void rope_kernel(
    const float* __restrict__ cosT, const float* __restrict__ sinT)
{
    int tid = blockIdx.x * blockDim.x + threadIdx.x;   // B*L*H*32 total
    int i = tid & 31;
    int h = (tid >> 5) & (HH - 1);
    int l = (tid >> 9) & (LL - 1);
    int b = tid >> 20;
    if (b >= BB) return;

    float c0 = cosT[l * DH + i];
    float s0 = sinT[l * DH + i];
    float c1 = cosT[l * DH + i + 32];
    float s1 = sinT[l * DH + i + 32];

    size_t base = ((size_t)(b * LL + l) * 3) * DD + h * DH;
#pragma unroll
    for (int sel = 0; sel < 2; sel++) {
        float* p = &g_qkv[base + (size_t)sel * DD];
        float t1 = p[i];
        float t2 = p[i + 32];
        p[i]      = t1 * c0 - t2 * s0;
        p[i + 32] = t2 * c1 + t1 * s1;
    }
}

// ---------------------------------------------------------------------------
// Flash attention: per (b,h), 64-query tile per block, iterate 64-row KV tiles.
// 256 threads as 16x16 grid of 4x4 microtiles. Online softmax.
// smem: Qt[d][q] 16KB, Kt[d][kv] 16KB (aliased as P[q][kv]), Vs[kv][d] 16KB.
// ---------------------------------------------------------------------------
__global__ __launch_bounds__(256) void flash_kernel()
{
    __shared__ float Qt[64][64];   // [d][qrow]
    __shared__ float Kt[64][64];   // [d][kvrow]  (reused as P[qrow][kvrow])
    __shared__ float Vs[64][64];   // [kvrow][d]

    const int tid = threadIdx.x;
    const int tx = tid & 15;
    const int ty = tid >> 4;
    const int bh = blockIdx.y;
    const int b = bh / HH;
    const int h = bh % HH;
    const int q0 = blockIdx.x * 64;
    const float scale = 0.125f;    // 1/sqrt(64)

    // ---- load Q tile (transposed into Qt[d][q]) ----
#pragma unroll
    for (int it = 0; it < 4; it++) {
        int f = tid + it * 256;          // float4 index 0..1023
        int r = f >> 4;                  // q row 0..63
        int dq = (f & 15) * 4;           // d offset
        size_t g = ((size_t)(b * LL + q0 + r) * 3) * DD + h * DH + dq;
        float4 v = *reinterpret_cast<const float4*>(&g_qkv[g]);
        Qt[dq + 0][r] = v.x; Qt[dq + 1][r] = v.y; Qt[dq + 2][r] = v.z; Qt[dq + 3][r] = v.w;
    }

    float o[4][4];
    float m[4], lsum[4];
#pragma unroll
    for (int i = 0; i < 4; i++) {
        m[i] = -INFINITY; lsum[i] = 0.f;
#pragma unroll
        for (int j = 0; j < 4; j++) o[i][j] = 0.f;
    }

    for (int kt0 = 0; kt0 < LL; kt0 += 64) {
        __syncthreads();   // previous iter's P/V reads complete
        // ---- load K (transposed) and V tiles ----
#pragma unroll
        for (int it = 0; it < 4; it++) {
            int f = tid + it * 256;
            int r = f >> 4;
            int dq = (f & 15) * 4;
            size_t gk = ((size_t)(b * LL + kt0 + r) * 3 + 1) * DD + h * DH + dq;
            size_t gv = ((size_t)(b * LL + kt0 + r) * 3 + 2) * DD + h * DH + dq;
            float4 kv = *reinterpret_cast<const float4*>(&g_qkv[gk]);
            float4 vv = *reinterpret_cast<const float4*>(&g_qkv[gv]);
            Kt[dq + 0][r] = kv.x; Kt[dq + 1][r] = kv.y; Kt[dq + 2][r] = kv.z; Kt[dq + 3][r] = kv.w;
            *reinterpret_cast<float4*>(&Vs[r][dq]) = vv;
        }
        __syncthreads();

        // ---- S = scale * Q K^T  (4x4 per thread) ----
        float s[4][4];
#pragma unroll
        for (int i = 0; i < 4; i++)
#pragma unroll
            for (int j = 0; j < 4; j++) s[i][j] = 0.f;

#pragma unroll 8
        for (int d = 0; d < 64; d++) {
            float4 q = *reinterpret_cast<const float4*>(&Qt[d][ty * 4]);
            float4 k = *reinterpret_cast<const float4*>(&Kt[d][tx * 4]);
            float qa[4] = {q.x, q.y, q.z, q.w};
            float ka[4] = {k.x, k.y, k.z, k.w};
#pragma unroll
            for (int i = 0; i < 4; i++)
#pragma unroll
                for (int j = 0; j < 4; j++) s[i][j] = fmaf(qa[i], ka[j], s[i][j]);
        }

        // ---- online softmax ----
        float mn[4], fac[4];
#pragma unroll
        for (int i = 0; i < 4; i++) {
            float tm = s[i][0] * scale;
#pragma unroll
            for (int j = 1; j < 4; j++) tm = fmaxf(tm, s[i][j] * scale);
            // reduce max across tx (16-lane segments)
#pragma unroll
            for (int off = 8; off >= 1; off >>= 1)
                tm = fmaxf(tm, __shfl_xor_sync(0xffffffffu, tm, off, 16));
            mn[i] = fmaxf(m[i], tm);
            fac[i] = __expf(m[i] - mn[i]);
            float ts = 0.f;
#pragma unroll
            for (int j = 0; j < 4; j++) {
                s[i][j] = __expf(s[i][j] * scale - mn[i]);
                ts += s[i][j];
            }
#pragma unroll
            for (int off = 8; off >= 1; off >>= 1)
                ts += __shfl_xor_sync(0xffffffffu, ts, off, 16);
            lsum[i] = lsum[i] * fac[i] + ts;
            m[i] = mn[i];
#pragma unroll
            for (int j = 0; j < 4; j++) o[i][j] *= fac[i];
        }

        __syncthreads();   // everyone done reading Kt (S compute)
        // ---- write P into Kt buffer (as P[q][kv]) ----
#pragma unroll
        for (int i = 0; i < 4; i++) {
            float4 v = make_float4(s[i][0], s[i][1], s[i][2], s[i][3]);
            *reinterpret_cast<float4*>(&Kt[ty * 4 + i][tx * 4]) = v;
        }
        __syncthreads();

        // ---- O += P @ V ----
#pragma unroll 8
        for (int kv = 0; kv < 64; kv++) {
            float4 vv = *reinterpret_cast<const float4*>(&Vs[kv][tx * 4]);
            float va[4] = {vv.x, vv.y, vv.z, vv.w};
#pragma unroll
            for (int i = 0; i < 4; i++) {
                float pv = Kt[ty * 4 + i][kv];
#pragma unroll
                for (int j = 0; j < 4; j++) o[i][j] = fmaf(pv, va[j], o[i][j]);
            }
        }
    }

    // ---- epilogue: normalize, store to g_att[b,l,h,dh] ----
#pragma unroll
    for (int i = 0; i < 4; i++) {
        float inv = 1.f / lsum[i];
        float4 v = make_float4(o[i][0] * inv, o[i][1] * inv, o[i][2] * inv, o[i][3] * inv);
        size_t g = ((size_t)(b * LL + q0 + ty * 4 + i) * HH + h) * DH + tx * 4;
        *reinterpret_cast<float4*>(&g_att[g]) = v;
    }
}

// ---------------------------------------------------------------------------
extern "C" void kernel_launch(void* const* d_in, const int* in_sizes, int n_in,
                              void* d_out, int out_size)
{
    const float* x     = (const float*)d_in[0];
    const float* cosT  = (const float*)d_in[1];
    const float* sinT  = (const float*)d_in[2];
    const float* w_qkv = (const float*)d_in[3];
    const float* w_o   = (const float*)d_in[4];
    float* out = (float*)d_out;

    float* qkv_ptr = nullptr;
    float* att_ptr = nullptr;
    cudaGetSymbolAddress((void**)&qkv_ptr, g_qkv);
    cudaGetSymbolAddress((void**)&att_ptr, g_att);

    // 1. QKV projection: [4096,1024] @ [3072,1024]^T
    {
        dim3 grid(3 * DD / 64, ML / 64);
        gemm_abt_kernel<<<grid, 256>>>(x, w_qkv, qkv_ptr, ML, 3 * DD, DD);
    }
    // 2. RoPE on q,k
    {
        int threads = BB * LL * HH * 32;
        rope_kernel<<<threads / 256, 256>>>(cosT, sinT);
    }
    // 3. Flash attention
    {
        dim3 grid(LL / 64, BB * HH);
        flash_kernel<<<grid, 256>>>();
    }
    // 4. Output projection: [4096,1024] @ [1024,1024]^T
    {
        dim3 grid(DD / 64, ML / 64);
        gemm_abt_kernel<<<grid, 256>>>(att_ptr, w_o, out, ML, DD, DD);
    }
}

// round 2
// speedup vs baseline: 1.3848x; 1.3848x over previous
#include <cuda_runtime.h>
#include <math.h>

#define BB 2
#define LL 2048
#define DD 1024
#define HH 16
#define DH 64
#define ML (BB*LL)          // 4096 rows

// Scratch (allocation-free rule: device globals)
__device__ float g_qkv[ML * 3 * DD];        // [b,l,3,h,dh]  (q,k unroped; v source)
__device__ float g_qt [BB * HH * DH * LL];  // [b,h,d,l]  roped Q, transposed
__device__ float g_kt [BB * HH * DH * LL];  // [b,h,d,l]  roped K, transposed
__device__ float g_v  [BB * HH * LL * DH];  // [b,h,l,d]
__device__ float g_att[ML * DD];            // [b,l,h,dh]

// ---------------------------------------------------------------------------
// Tiled GEMM: C[M,N] = A[M,K] @ W[N,K]^T, fp32.
// BM=BN=128, BK=16, 256 threads, 8x8 microtile (split 4+4 cols/rows 64 apart),
// double-buffered smem.
// ---------------------------------------------------------------------------
__global__ __launch_bounds__(256, 2) void gemm_abt_kernel(
    const float* __restrict__ A, const float* __restrict__ W, float* __restrict__ C,
    int M, int N, int K)
{
    __shared__ float As[2][16][132];  // [buf][k][m], padded
    __shared__ float Ws[2][16][132];  // [buf][k][n]

    const int tid = threadIdx.x;
    const int tx = tid & 15;
    const int ty = tid >> 4;
    const int m0 = blockIdx.y * 128;
    const int n0 = blockIdx.x * 128;

    const int r0 = tid >> 2;          // 0..63
    const int kq = (tid & 3) * 4;     // 0,4,8,12

    float acc[8][8];
#pragma unroll
    for (int i = 0; i < 8; i++)
#pragma unroll
        for (int j = 0; j < 8; j++) acc[i][j] = 0.f;

    const int nk = K >> 4;
    float4 pa[2], pw[2];

    // preload tile 0
#pragma unroll
    for (int it = 0; it < 2; it++) {
        int r = r0 + it * 64;
        pa[it] = *reinterpret_cast<const float4*>(&A[(size_t)(m0 + r) * K + kq]);
        pw[it] = *reinterpret_cast<const float4*>(&W[(size_t)(n0 + r) * K + kq]);
    }
#pragma unroll
    for (int it = 0; it < 2; it++) {
        int r = r0 + it * 64;
        As[0][kq + 0][r] = pa[it].x; As[0][kq + 1][r] = pa[it].y;
        As[0][kq + 2][r] = pa[it].z; As[0][kq + 3][r] = pa[it].w;
        Ws[0][kq + 0][r] = pw[it].x; Ws[0][kq + 1][r] = pw[it].y;
        Ws[0][kq + 2][r] = pw[it].z; Ws[0][kq + 3][r] = pw[it].w;
    }
    __syncthreads();

    int buf = 0;
    for (int t = 1; t < nk; t++) {
        const int kt = t * 16;
#pragma unroll
        for (int it = 0; it < 2; it++) {
            int r = r0 + it * 64;
            pa[it] = *reinterpret_cast<const float4*>(&A[(size_t)(m0 + r) * K + kt + kq]);
            pw[it] = *reinterpret_cast<const float4*>(&W[(size_t)(n0 + r) * K + kt + kq]);
        }
#pragma unroll
        for (int k = 0; k < 16; k++) {
            float4 a0 = *reinterpret_cast<const float4*>(&As[buf][k][ty * 4]);
            float4 a1 = *reinterpret_cast<const float4*>(&As[buf][k][64 + ty * 4]);
            float4 w0 = *reinterpret_cast<const float4*>(&Ws[buf][k][tx * 4]);
            float4 w1 = *reinterpret_cast<const float4*>(&Ws[buf][k][64 + tx * 4]);
            float ar[8] = {a0.x, a0.y, a0.z, a0.w, a1.x, a1.y, a1.z, a1.w};
            float wr[8] = {w0.x, w0.y, w0.z, w0.w, w1.x, w1.y, w1.z, w1.w};
#pragma unroll
            for (int i = 0; i < 8; i++)
#pragma unroll
                for (int j = 0; j < 8; j++) acc[i][j] = fmaf(ar[i], wr[j], acc[i][j]);
        }
        const int nb = buf ^ 1;
#pragma unroll
        for (int it = 0; it < 2; it++) {
            int r = r0 + it * 64;
            As[nb][kq + 0][r] = pa[it].x; As[nb][kq + 1][r] = pa[it].y;
            As[nb][kq + 2][r] = pa[it].z; As[nb][kq + 3][r] = pa[it].w;
            Ws[nb][kq + 0][r] = pw[it].x; Ws[nb][kq + 1][r] = pw[it].y;
            Ws[nb][kq + 2][r] = pw[it].z; Ws[nb][kq + 3][r] = pw[it].w;
        }
        __syncthreads();
        buf = nb;
    }
    // final tile compute
#pragma unroll
    for (int k = 0; k < 16; k++) {
        float4 a0 = *reinterpret_cast<const float4*>(&As[buf][k][ty * 4]);
        float4 a1 = *reinterpret_cast<const float4*>(&As[buf][k][64 + ty * 4]);
        float4 w0 = *reinterpret_cast<const float4*>(&Ws[buf][k][tx * 4]);
        float4 w1 = *reinterpret_cast<const float4*>(&Ws[buf][k][64 + tx * 4]);
        float ar[8] = {a0.x, a0.y, a0.z, a0.w, a1.x, a1.y, a1.z, a1.w};
        float wr[8] = {w0.x, w0.y, w0.z, w0.w, w1.x, w1.y, w1.z, w1.w};
#pragma unroll
        for (int i = 0; i < 8; i++)
#pragma unroll
            for (int j = 0; j < 8; j++) acc[i][j] = fmaf(ar[i], wr[j], acc[i][j]);
    }

#pragma unroll
    for (int i = 0; i < 8; i++) {
        int m = m0 + ty * 4 + (i & 3) + (i >> 2) * 64;
        *reinterpret_cast<float4*>(&C[(size_t)m * N + n0 + tx * 4]) =
            make_float4(acc[i][0], acc[i][1], acc[i][2], acc[i][3]);
        *reinterpret_cast<float4*>(&C[(size_t)m * N + n0 + 64 + tx * 4]) =
            make_float4(acc[i][4], acc[i][5], acc[i][6], acc[i][7]);
    }
}

// ---------------------------------------------------------------------------
// RoPE + transpose: reads unroped q,k from g_qkv, applies rope, writes
// g_qt/g_kt in [b,h,d,l] layout. Also copies v into g_v [b,h,l,d].
// One block per (bh, 64-l tile), 256 threads.
// ---------------------------------------------------------------------------
__global__ __launch_bounds__(256) void rope_transpose_kernel(
    const float* __restrict__ cosT, const float* __restrict__ sinT)
{
    __shared__ float Qs[64][65];
    __shared__ float Ks[64][65];

    const int tid = threadIdx.x;
    const int bh = blockIdx.y;
    const int b = bh >> 4;
    const int h = bh & 15;
    const int l0 = blockIdx.x * 64;

    // rope into smem tiles (l-major)
#pragma unroll
    for (int it = 0; it < 8; it++) {
        int p = tid + it * 256;        // 0..2047
        int l = p >> 5;
        int i = p & 31;
        int lg = l0 + l;
        size_t base = ((size_t)(b * LL + lg) * 3) * DD + h * 64;
        float c0 = cosT[lg * 64 + i],      s0 = sinT[lg * 64 + i];
        float c1 = cosT[lg * 64 + i + 32], s1 = sinT[lg * 64 + i + 32];
        float q1 = g_qkv[base + i], q2 = g_qkv[base + i + 32];
        Qs[l][i]      = q1 * c0 - q2 * s0;
        Qs[l][i + 32] = q2 * c1 + q1 * s1;
        float k1 = g_qkv[base + DD + i], k2 = g_qkv[base + DD + i + 32];
        Ks[l][i]      = k1 * c0 - k2 * s0;
        Ks[l][i + 32] = k2 * c1 + k1 * s1;
    }
    // v copy (coalesced both ways, no transpose)
#pragma unroll
    for (int it = 0; it < 4; it++) {
        int f = tid + it * 256;
        int r = f >> 4;
        int dq = (f & 15) * 4;
        size_t src = ((size_t)(b * LL + l0 + r) * 3 + 2) * DD + h * 64 + dq;
        *reinterpret_cast<float4*>(&g_v[((size_t)bh * LL + l0 + r) * 64 + dq]) =
            *reinterpret_cast<const float4*>(&g_qkv[src]);
    }
    __syncthreads();
    // transposed write-out [d][l]
    float* qt  = g_qt + (size_t)bh * DH * LL;
    float* ktp = g_kt + (size_t)bh * DH * LL;
#pragma unroll
    for (int it = 0; it < 4; it++) {
        int f = tid + it * 256;
        int d = f >> 4;
        int lq = (f & 15) * 4;
        float4 vq = make_float4(Qs[lq][d], Qs[lq + 1][d], Qs[lq + 2][d], Qs[lq + 3][d]);
        float4 vk = make_float4(Ks[lq][d], Ks[lq + 1][d], Ks[lq + 2][d], Ks[lq + 3][d]);
        *reinterpret_cast<float4*>(&qt [(size_t)d * LL + l0 + lq]) = vq;
        *reinterpret_cast<float4*>(&ktp[(size_t)d * LL + l0 + lq]) = vk;
    }
}

// ---------------------------------------------------------------------------
// Flash attention: per (b,h), 128-query tile, 64-kv tiles. 256 threads,
// 8(q)x4 microtiles. Online softmax. All smem accesses vec4 + conflict-free.
// ---------------------------------------------------------------------------
#define SM_QT   0
#define SM_KT   (64*128)
#define SM_VS   (SM_KT + 64*64)
#define SM_P    (SM_VS + 64*68)
#define SMEM_FLASH_FLOATS (SM_P + 128*68)

__global__ __launch_bounds__(256, 2) void flash_kernel()
{
    extern __shared__ float sm[];
    float* Qt = sm + SM_QT;   // [64 d][128 q]
    float* Kt = sm + SM_KT;   // [64 d][64 kv]
    float* Vs = sm + SM_VS;   // [64 kv][68]
    float* Pm = sm + SM_P;    // [128 q][68]

    const int tid = threadIdx.x;
    const int tx = tid & 15;
    const int ty = tid >> 4;
    const int bh = blockIdx.y;
    const int b = bh >> 4;
    const int h = bh & 15;
    const int q0 = blockIdx.x * 128;
    const float scale = 0.125f;   // 1/sqrt(64)

    const float* qtp = g_qt + (size_t)bh * DH * LL;
    const float* ktp = g_kt + (size_t)bh * DH * LL;
    const float* vp  = g_v  + (size_t)bh * LL * DH;

    // load Q tile [d][q0..q0+127]
#pragma unroll
    for (int it = 0; it < 8; it++) {
        int f = tid + it * 256;
        int d = f >> 5;
        int c = (f & 31) * 4;
        *reinterpret_cast<float4*>(&Qt[d * 128 + c]) =
            *reinterpret_cast<const float4*>(&qtp[(size_t)d * LL + q0 + c]);
    }

    float o[8][4];
    float m[8], lsum[8];
#pragma unroll
    for (int i = 0; i < 8; i++) {
        m[i] = -INFINITY; lsum[i] = 0.f;
#pragma unroll
        for (int j = 0; j < 4; j++) o[i][j] = 0.f;
    }

    for (int kt0 = 0; kt0 < LL; kt0 += 64) {
        __syncthreads();   // prior PV reads of Vs/Pm done; Kt free
        // load K [d][kv], V [kv][d]
#pragma unroll
        for (int it = 0; it < 4; it++) {
            int f = tid + it * 256;
            int d = f >> 4;
            int c = (f & 15) * 4;
            *reinterpret_cast<float4*>(&Kt[d * 64 + c]) =
                *reinterpret_cast<const float4*>(&ktp[(size_t)d * LL + kt0 + c]);
            *reinterpret_cast<float4*>(&Vs[d * 68 + c]) =
                *reinterpret_cast<const float4*>(&vp[(size_t)(kt0 + d) * DH + c]);
        }
        __syncthreads();

        // ---- S = Q K^T ----
        float s[8][4];
#pragma unroll
        for (int i = 0; i < 8; i++)
#pragma unroll
            for (int j = 0; j < 4; j++) s[i][j] = 0.f;

#pragma unroll 4
        for (int d = 0; d < 64; d++) {
            float4 qa0 = *reinterpret_cast<const float4*>(&Qt[d * 128 + ty * 4]);
            float4 qa1 = *reinterpret_cast<const float4*>(&Qt[d * 128 + 64 + ty * 4]);
            float4 kv  = *reinterpret_cast<const float4*>(&Kt[d * 64 + tx * 4]);
            float qa[8] = {qa0.x, qa0.y, qa0.z, qa0.w, qa1.x, qa1.y, qa1.z, qa1.w};
            float ka[4] = {kv.x, kv.y, kv.z, kv.w};
#pragma unroll
            for (int i = 0; i < 8; i++)
#pragma unroll
                for (int j = 0; j < 4; j++) s[i][j] = fmaf(qa[i], ka[j], s[i][j]);
        }

        // ---- online softmax (rows) ----
#pragma unroll
        for (int i = 0; i < 8; i++) {
            float tm = fmaxf(fmaxf(s[i][0], s[i][1]), fmaxf(s[i][2], s[i][3])) * scale;
#pragma unroll
            for (int off = 8; off >= 1; off >>= 1)
                tm = fmaxf(tm, __shfl_xor_sync(0xffffffffu, tm, off, 16));
            float mn = fmaxf(m[i], tm);
            float fac = __expf(m[i] - mn);
            float ts = 0.f;
#pragma unroll
            for (int j = 0; j < 4; j++) {
                s[i][j] = __expf(s[i][j] * scale - mn);
                ts += s[i][j];
            }
#pragma unroll
            for (int off = 8; off >= 1; off >>= 1)
                ts += __shfl_xor_sync(0xffffffffu, ts, off, 16);
            lsum[i] = lsum[i] * fac + ts;
            m[i] = mn;
#pragma unroll
            for (int j = 0; j < 4; j++) o[i][j] *= fac;
        }

        // ---- write P[q][kv] ----
#pragma unroll
        for (int i = 0; i < 8; i++) {
            int ri = ty * 4 + (i & 3) + (i >> 2) * 64;
            *reinterpret_cast<float4*>(&Pm[ri * 68 + tx * 4]) =
                make_float4(s[i][0], s[i][1], s[i][2], s[i][3]);
        }
        __syncthreads();

        // ---- O += P @ V ----
#pragma unroll 2
        for (int kv0 = 0; kv0 < 64; kv0 += 4) {
            float va[4][4];
#pragma unroll
            for (int jj = 0; jj < 4; jj++) {
                float4 vv = *reinterpret_cast<const float4*>(&Vs[(kv0 + jj) * 68 + tx * 4]);
                va[jj][0] = vv.x; va[jj][1] = vv.y; va[jj][2] = vv.z; va[jj][3] = vv.w;
            }
#pragma unroll
            for (int i = 0; i < 8; i++) {
                int ri = ty * 4 + (i & 3) + (i >> 2) * 64;
                float4 pv = *reinterpret_cast<const float4*>(&Pm[ri * 68 + kv0]);
                float pa[4] = {pv.x, pv.y, pv.z, pv.w};
#pragma unroll
                for (int jj = 0; jj < 4; jj++)
#pragma unroll
                    for (int j = 0; j < 4; j++)
                        o[i][j] = fmaf(pa[jj], va[jj][j], o[i][j]);
            }
        }
    }

    // ---- epilogue ----
#pragma unroll
    for (int i = 0; i < 8; i++) {
        int ri = ty * 4 + (i & 3) + (i >> 2) * 64;
        float inv = 1.f / lsum[i];
        size_t g = ((size_t)(b * LL + q0 + ri) * HH + h) * DH + tx * 4;
        *reinterpret_cast<float4*>(&g_att[g]) =
            make_float4(o[i][0] * inv, o[i][1] * inv, o[i][2] * inv, o[i][3] * inv);
    }
}

// ---------------------------------------------------------------------------
extern "C" void kernel_launch(void* const* d_in, const int* in_sizes, int n_in,
                              void* d_out, int out_size)
{
    const float* x     = (const float*)d_in[0];
    const float* cosT  = (const float*)d_in[1];
    const float* sinT  = (const float*)d_in[2];
    const float* w_qkv = (const float*)d_in[3];
    const float* w_o   = (const float*)d_in[4];
    float* out = (float*)d_out;

    float* qkv_ptr = nullptr;
    float* att_ptr = nullptr;
    cudaGetSymbolAddress((void**)&qkv_ptr, g_qkv);
    cudaGetSymbolAddress((void**)&att_ptr, g_att);

    static bool attr_done = false;
    if (!attr_done) {
        cudaFuncSetAttribute(flash_kernel,
                             cudaFuncAttributeMaxDynamicSharedMemorySize,
                             SMEM_FLASH_FLOATS * sizeof(float));
        attr_done = true;
    }

    // 1. QKV projection: [4096,1024] @ [3072,1024]^T
    {
        dim3 grid(3 * DD / 128, ML / 128);
        gemm_abt_kernel<<<grid, 256>>>(x, w_qkv, qkv_ptr, ML, 3 * DD, DD);
    }
    // 2. RoPE + transpose to [b,h,d,l], v to [b,h,l,d]
    {
        dim3 grid(LL / 64, BB * HH);
        rope_transpose_kernel<<<grid, 256>>>(cosT, sinT);
    }
    // 3. Flash attention
    {
        dim3 grid(LL / 128, BB * HH);
        flash_kernel<<<grid, 256, SMEM_FLASH_FLOATS * sizeof(float)>>>();
    }
    // 4. Output projection: [4096,1024] @ [1024,1024]^T
    {
        dim3 grid(DD / 128, ML / 128);
        gemm_abt_kernel<<<grid, 256>>>(att_ptr, w_o, out, ML, DD, DD);
    }
}

// round 4
// speedup vs baseline: 1.7952x; 1.2964x over previous
#include <cuda_runtime.h>
#include <cuda_bf16.h>
#include <math.h>
#include <cstdint>

#define BB 2
#define LL 2048
#define DD 1024
#define HH 16
#define DH 64
#define ML (BB*LL)          // 4096 rows

// ---------------------------------------------------------------------------
// Scratch (allocation-free rule: device globals)
// ---------------------------------------------------------------------------
__device__ float g_qkv[ML * 3 * DD];        // [b,l,3,h,dh]
__device__ float g_qt [BB * HH * DH * LL];  // [b,h,d,l]
__device__ float g_kt [BB * HH * DH * LL];  // [b,h,d,l]
__device__ float g_v  [BB * HH * LL * DH];  // [b,h,l,d]
__device__ float g_att[ML * DD];            // [b,l,h,dh]

// bf16 split operands for mma GEMMs
__device__ __nv_bfloat16 g_xh[ML * DD],      g_xl[ML * DD];
__device__ __nv_bfloat16 g_wqh[3 * DD * DD], g_wql[3 * DD * DD];
__device__ __nv_bfloat16 g_woh[DD * DD],     g_wol[DD * DD];
__device__ __nv_bfloat16 g_ah[ML * DD],      g_al[ML * DD];

// ---------------------------------------------------------------------------
// PTX helpers (sm_100-safe: no 'a'-gated features)
// ---------------------------------------------------------------------------
__device__ __forceinline__ uint32_t smem_u32(const void* p) {
    uint32_t a;
    asm("{ .reg .u64 t; cvta.to.shared.u64 t, %1; cvt.u32.u64 %0, t; }" : "=r"(a) : "l"(p));
    return a;
}
#define CP_ASYNC16(dst, src) \
    asm volatile("cp.async.cg.shared.global [%0], [%1], 16;" :: "r"(dst), "l"(src))
#define CP_COMMIT()  asm volatile("cp.async.commit_group;")
#define CP_WAIT0()   asm volatile("cp.async.wait_group 0;" ::: "memory")
#define CP_WAIT1()   asm volatile("cp.async.wait_group 1;" ::: "memory")

__device__ __forceinline__ void ldsm_x4(uint32_t* r, uint32_t addr) {
    asm volatile("ldmatrix.sync.aligned.m8n8.x4.shared.b16 {%0,%1,%2,%3}, [%4];"
                 : "=r"(r[0]), "=r"(r[1]), "=r"(r[2]), "=r"(r[3]) : "r"(addr));
}
__device__ __forceinline__ void mma_bf16(float* d, const uint32_t* a,
                                         uint32_t b0, uint32_t b1) {
    asm volatile(
        "mma.sync.aligned.m16n8k16.row.col.f32.bf16.bf16.f32 "
        "{%0,%1,%2,%3}, {%4,%5,%6,%7}, {%8,%9}, {%0,%1,%2,%3};"
        : "+f"(d[0]), "+f"(d[1]), "+f"(d[2]), "+f"(d[3])
        : "r"(a[0]), "r"(a[1]), "r"(a[2]), "r"(a[3]), "r"(b0), "r"(b1));
}

// ---------------------------------------------------------------------------
// Split fp32 -> bf16 hi/lo
// ---------------------------------------------------------------------------
__global__ __launch_bounds__(256) void split_kernel(
    const float* __restrict__ src, __nv_bfloat16* __restrict__ hi,
    __nv_bfloat16* __restrict__ lo, int n4)
{
    int i = blockIdx.x * blockDim.x + threadIdx.x;
    if (i >= n4) return;
    float4 v = reinterpret_cast<const float4*>(src)[i];
    __nv_bfloat16 h0 = __float2bfloat16_rn(v.x), h1 = __float2bfloat16_rn(v.y);
    __nv_bfloat16 h2 = __float2bfloat16_rn(v.z), h3 = __float2bfloat16_rn(v.w);
    __nv_bfloat162 hh0 = {h0, h1}, hh1 = {h2, h3};
    __nv_bfloat162 ll0 = {__float2bfloat16_rn(v.x - __bfloat162float(h0)),
                          __float2bfloat16_rn(v.y - __bfloat162float(h1))};
    __nv_bfloat162 ll1 = {__float2bfloat16_rn(v.z - __bfloat162float(h2)),
                          __float2bfloat16_rn(v.w - __bfloat162float(h3))};
    reinterpret_cast<__nv_bfloat162*>(hi)[i * 2]     = hh0;
    reinterpret_cast<__nv_bfloat162*>(hi)[i * 2 + 1] = hh1;
    reinterpret_cast<__nv_bfloat162*>(lo)[i * 2]     = ll0;
    reinterpret_cast<__nv_bfloat162*>(lo)[i * 2 + 1] = ll1;
}

// ---------------------------------------------------------------------------
// mma.sync GEMM: C[M,N] = A[M,K] @ W[N,K]^T via bf16x3 split.
// 128x128 CTA tile, 8 warps as 2(m)x4(n), warp tile 64x32.
// K-chunk 32, double-buffered cp.async. Rows padded to 80B (conflict-free
// ldmatrix: bank step 20).
// ---------------------------------------------------------------------------
#define KC 32
#define ROWB 80                       // bytes per smem row (64 data + 16 pad)
#define TILE_B (128 * ROWB)           // 10240 B
#define BUF_B  (4 * TILE_B)           // Ah,Al,Wh,Wl
#define GEMM_SMEM_DYN (2 * BUF_B)     // 81920 B

__global__ __launch_bounds__(256, 2) void gemm_mma_kernel(
    const __nv_bfloat16* __restrict__ Ah, const __nv_bfloat16* __restrict__ Al,
    const __nv_bfloat16* __restrict__ Wh, const __nv_bfloat16* __restrict__ Wl,
    float* __restrict__ C, int M, int N, int K)
{
    extern __shared__ uint8_t sm8[];
    const uint32_t sbase = smem_u32(sm8);

    const int tid  = threadIdx.x;
    const int wid  = tid >> 5;
    const int lane = tid & 31;
    const int m0 = blockIdx.y * 128;
    const int n0 = blockIdx.x * 128;
    const int wm = (wid & 1) * 64;      // warp m offset
    const int wn = (wid >> 1) * 32;     // warp n offset

    float acc[4][4][4];
#pragma unroll
    for (int i = 0; i < 4; i++)
#pragma unroll
        for (int j = 0; j < 4; j++)
#pragma unroll
            for (int q = 0; q < 4; q++) acc[i][j][q] = 0.f;

    // ldmatrix per-lane relative offsets
    const uint32_t aOff = (uint32_t)((wm + (lane & 15)) * ROWB + (lane >> 4) * 16);
    const uint32_t bOff = (uint32_t)((wn + (lane & 7) + ((lane >> 4) << 3)) * ROWB
                                     + ((lane >> 3) & 1) * 16);

    const int nc = K / KC;

    auto issue_loads = [&](int c, int buf) {
        const int kc = c * KC;
        const uint32_t dstb = sbase + buf * BUF_B;
#pragma unroll
        for (int it = 0; it < 8; it++) {
            int op = tid + it * 256;
            int t = op >> 9;             // tile 0..3
            int r = (op >> 2) & 127;     // row
            int p = op & 3;              // 16B piece
            const __nv_bfloat16* srcp;
            if (t == 0)      srcp = Ah + (size_t)(m0 + r) * K + kc + p * 8;
            else if (t == 1) srcp = Al + (size_t)(m0 + r) * K + kc + p * 8;
            else if (t == 2) srcp = Wh + (size_t)(n0 + r) * K + kc + p * 8;
            else             srcp = Wl + (size_t)(n0 + r) * K + kc + p * 8;
            CP_ASYNC16(dstb + t * TILE_B + r * ROWB + p * 16, srcp);
        }
        CP_COMMIT();
    };

    issue_loads(0, 0);

    for (int c = 0; c < nc; c++) {
        if (c + 1 < nc) { issue_loads(c + 1, (c + 1) & 1); CP_WAIT1(); }
        else            { CP_WAIT0(); }
        __syncthreads();

        const uint32_t dstb = sbase + (c & 1) * BUF_B;
#pragma unroll
        for (int pass = 0; pass < 3; pass++) {
            const uint32_t aBase = dstb + (pass == 2 ? TILE_B : 0);
            const uint32_t bBase = dstb + 2 * TILE_B + (pass == 1 ? TILE_B : 0);
#pragma unroll
            for (int step = 0; step < 2; step++) {
                uint32_t aF[4][4];
                uint32_t bF[8];
#pragma unroll
                for (int mt = 0; mt < 4; mt++)
                    ldsm_x4(aF[mt], aBase + aOff + mt * 16 * ROWB + step * 32);
#pragma unroll
                for (int nt2 = 0; nt2 < 2; nt2++)
                    ldsm_x4(bF + nt2 * 4, bBase + bOff + nt2 * 16 * ROWB + step * 32);
#pragma unroll
                for (int mt = 0; mt < 4; mt++)
#pragma unroll
                    for (int nt = 0; nt < 4; nt++) {
                        int bi = (nt >> 1) * 4 + (nt & 1) * 2;
                        mma_bf16(acc[mt][nt], aF[mt], bF[bi], bF[bi + 1]);
                    }
            }
        }
        __syncthreads();
    }

    // epilogue: d0,d1 -> (row t/4, col (t%4)*2); d2,d3 -> row+8
    const int rb = lane >> 2;
    const int cb = (lane & 3) * 2;
#pragma unroll
    for (int mt = 0; mt < 4; mt++)
#pragma unroll
        for (int nt = 0; nt < 4; nt++) {
            int row = m0 + wm + mt * 16 + rb;
            int col = n0 + wn + nt * 8 + cb;
            *reinterpret_cast<float2*>(&C[(size_t)row * N + col]) =
                make_float2(acc[mt][nt][0], acc[mt][nt][1]);
            *reinterpret_cast<float2*>(&C[(size_t)(row + 8) * N + col]) =
                make_float2(acc[mt][nt][2], acc[mt][nt][3]);
        }
}

// ---------------------------------------------------------------------------
// RoPE + transpose (unchanged from R2)
// ---------------------------------------------------------------------------
__global__ __launch_bounds__(256) void rope_transpose_kernel(
    const float* __restrict__ cosT, const float* __restrict__ sinT)
{
    __shared__ float Qs[64][65];
    __shared__ float Ks[64][65];

    const int tid = threadIdx.x;
    const int bh = blockIdx.y;
    const int b = bh >> 4;
    const int h = bh & 15;
    const int l0 = blockIdx.x * 64;

#pragma unroll
    for (int it = 0; it < 8; it++) {
        int p = tid + it * 256;
        int l = p >> 5;
        int i = p & 31;
        int lg = l0 + l;
        size_t base = ((size_t)(b * LL + lg) * 3) * DD + h * 64;
        float c0 = cosT[lg * 64 + i],      s0 = sinT[lg * 64 + i];
        float c1 = cosT[lg * 64 + i + 32], s1 = sinT[lg * 64 + i + 32];
        float q1 = g_qkv[base + i], q2 = g_qkv[base + i + 32];
        Qs[l][i]      = q1 * c0 - q2 * s0;
        Qs[l][i + 32] = q2 * c1 + q1 * s1;
        float k1 = g_qkv[base + DD + i], k2 = g_qkv[base + DD + i + 32];
        Ks[l][i]      = k1 * c0 - k2 * s0;
        Ks[l][i + 32] = k2 * c1 + k1 * s1;
    }
#pragma unroll
    for (int it = 0; it < 4; it++) {
        int f = tid + it * 256;
        int r = f >> 4;
        int dq = (f & 15) * 4;
        size_t src = ((size_t)(b * LL + l0 + r) * 3 + 2) * DD + h * 64 + dq;
        *reinterpret_cast<float4*>(&g_v[((size_t)bh * LL + l0 + r) * 64 + dq]) =
            *reinterpret_cast<const float4*>(&g_qkv[src]);
    }
    __syncthreads();
    float* qt  = g_qt + (size_t)bh * DH * LL;
    float* ktp = g_kt + (size_t)bh * DH * LL;
#pragma unroll
    for (int it = 0; it < 4; it++) {
        int f = tid + it * 256;
        int d = f >> 4;
        int lq = (f & 15) * 4;
        float4 vq = make_float4(Qs[lq][d], Qs[lq + 1][d], Qs[lq + 2][d], Qs[lq + 3][d]);
        float4 vk = make_float4(Ks[lq][d], Ks[lq + 1][d], Ks[lq + 2][d], Ks[lq + 3][d]);
        *reinterpret_cast<float4*>(&qt [(size_t)d * LL + l0 + lq]) = vq;
        *reinterpret_cast<float4*>(&ktp[(size_t)d * LL + l0 + lq]) = vk;
    }
}

// ---------------------------------------------------------------------------
// Flash attention (unchanged from R2, fp32)
// ---------------------------------------------------------------------------
#define SM_QT   0
#define SM_KT   (64*128)
#define SM_VS   (SM_KT + 64*64)
#define SM_P    (SM_VS + 64*68)
#define SMEM_FLASH_FLOATS (SM_P + 128*68)

__global__ __launch_bounds__(256, 2) void flash_kernel()
{
    extern __shared__ float sm[];
    float* Qt = sm + SM_QT;
    float* Kt = sm + SM_KT;
    float* Vs = sm + SM_VS;
    float* Pm = sm + SM_P;

    const int tid = threadIdx.x;
    const int tx = tid & 15;
    const int ty = tid >> 4;
    const int bh = blockIdx.y;
    const int b = bh >> 4;
    const int h = bh & 15;
    const int q0 = blockIdx.x * 128;
    const float scale = 0.125f;

    const float* qtp = g_qt + (size_t)bh * DH * LL;
    const float* ktp = g_kt + (size_t)bh * DH * LL;
    const float* vp  = g_v  + (size_t)bh * LL * DH;

#pragma unroll
    for (int it = 0; it < 8; it++) {
        int f = tid + it * 256;
        int d = f >> 5;
        int c = (f & 31) * 4;
        *reinterpret_cast<float4*>(&Qt[d * 128 + c]) =
            *reinterpret_cast<const float4*>(&qtp[(size_t)d * LL + q0 + c]);
    }

    float o[8][4];
    float m[8], lsum[8];
#pragma unroll
    for (int i = 0; i < 8; i++) {
        m[i] = -INFINITY; lsum[i] = 0.f;
#pragma unroll
        for (int j = 0; j < 4; j++) o[i][j] = 0.f;
    }

    for (int kt0 = 0; kt0 < LL; kt0 += 64) {
        __syncthreads();
#pragma unroll
        for (int it = 0; it < 4; it++) {
            int f = tid + it * 256;
            int d = f >> 4;
            int c = (f & 15) * 4;
            *reinterpret_cast<float4*>(&Kt[d * 64 + c]) =
                *reinterpret_cast<const float4*>(&ktp[(size_t)d * LL + kt0 + c]);
            *reinterpret_cast<float4*>(&Vs[d * 68 + c]) =
                *reinterpret_cast<const float4*>(&vp[(size_t)(kt0 + d) * DH + c]);
        }
        __syncthreads();

        float s[8][4];
#pragma unroll
        for (int i = 0; i < 8; i++)
#pragma unroll
            for (int j = 0; j < 4; j++) s[i][j] = 0.f;

#pragma unroll 4
        for (int d = 0; d < 64; d++) {
            float4 qa0 = *reinterpret_cast<const float4*>(&Qt[d * 128 + ty * 4]);
            float4 qa1 = *reinterpret_cast<const float4*>(&Qt[d * 128 + 64 + ty * 4]);
            float4 kv  = *reinterpret_cast<const float4*>(&Kt[d * 64 + tx * 4]);
            float qa[8] = {qa0.x, qa0.y, qa0.z, qa0.w, qa1.x, qa1.y, qa1.z, qa1.w};
            float ka[4] = {kv.x, kv.y, kv.z, kv.w};
#pragma unroll
            for (int i = 0; i < 8; i++)
#pragma unroll
                for (int j = 0; j < 4; j++) s[i][j] = fmaf(qa[i], ka[j], s[i][j]);
        }

#pragma unroll
        for (int i = 0; i < 8; i++) {
            float tm = fmaxf(fmaxf(s[i][0], s[i][1]), fmaxf(s[i][2], s[i][3])) * scale;
#pragma unroll
            for (int off = 8; off >= 1; off >>= 1)
                tm = fmaxf(tm, __shfl_xor_sync(0xffffffffu, tm, off, 16));
            float mn = fmaxf(m[i], tm);
            float fac = __expf(m[i] - mn);
            float ts = 0.f;
#pragma unroll
            for (int j = 0; j < 4; j++) {
                s[i][j] = __expf(s[i][j] * scale - mn);
                ts += s[i][j];
            }
#pragma unroll
            for (int off = 8; off >= 1; off >>= 1)
                ts += __shfl_xor_sync(0xffffffffu, ts, off, 16);
            lsum[i] = lsum[i] * fac + ts;
            m[i] = mn;
#pragma unroll
            for (int j = 0; j < 4; j++) o[i][j] *= fac;
        }

#pragma unroll
        for (int i = 0; i < 8; i++) {
            int ri = ty * 4 + (i & 3) + (i >> 2) * 64;
            *reinterpret_cast<float4*>(&Pm[ri * 68 + tx * 4]) =
                make_float4(s[i][0], s[i][1], s[i][2], s[i][3]);
        }
        __syncthreads();

#pragma unroll 2
        for (int kv0 = 0; kv0 < 64; kv0 += 4) {
            float va[4][4];
#pragma unroll
            for (int jj = 0; jj < 4; jj++) {
                float4 vv = *reinterpret_cast<const float4*>(&Vs[(kv0 + jj) * 68 + tx * 4]);
                va[jj][0] = vv.x; va[jj][1] = vv.y; va[jj][2] = vv.z; va[jj][3] = vv.w;
            }
#pragma unroll
            for (int i = 0; i < 8; i++) {
                int ri = ty * 4 + (i & 3) + (i >> 2) * 64;
                float4 pv = *reinterpret_cast<const float4*>(&Pm[ri * 68 + kv0]);
                float pa[4] = {pv.x, pv.y, pv.z, pv.w};
#pragma unroll
                for (int jj = 0; jj < 4; jj++)
#pragma unroll
                    for (int j = 0; j < 4; j++)
                        o[i][j] = fmaf(pa[jj], va[jj][j], o[i][j]);
            }
        }
    }

#pragma unroll
    for (int i = 0; i < 8; i++) {
        int ri = ty * 4 + (i & 3) + (i >> 2) * 64;
        float inv = 1.f / lsum[i];
        size_t g = ((size_t)(b * LL + q0 + ri) * HH + h) * DH + tx * 4;
        *reinterpret_cast<float4*>(&g_att[g]) =
            make_float4(o[i][0] * inv, o[i][1] * inv, o[i][2] * inv, o[i][3] * inv);
    }
}

// ---------------------------------------------------------------------------
extern "C" void kernel_launch(void* const* d_in, const int* in_sizes, int n_in,
                              void* d_out, int out_size)
{
    const float* x     = (const float*)d_in[0];
    const float* cosT  = (const float*)d_in[1];
    const float* sinT  = (const float*)d_in[2];
    const float* w_qkv = (const float*)d_in[3];
    const float* w_o   = (const float*)d_in[4];
    float* out = (float*)d_out;

    float *qkv_ptr, *att_ptr;
    __nv_bfloat16 *xh, *xl, *wqh, *wql, *woh, *wol, *ah, *al;
    cudaGetSymbolAddress((void**)&qkv_ptr, g_qkv);
    cudaGetSymbolAddress((void**)&att_ptr, g_att);
    cudaGetSymbolAddress((void**)&xh, g_xh);   cudaGetSymbolAddress((void**)&xl, g_xl);
    cudaGetSymbolAddress((void**)&wqh, g_wqh); cudaGetSymbolAddress((void**)&wql, g_wql);
    cudaGetSymbolAddress((void**)&woh, g_woh); cudaGetSymbolAddress((void**)&wol, g_wol);
    cudaGetSymbolAddress((void**)&ah, g_ah);   cudaGetSymbolAddress((void**)&al, g_al);

    static bool attr_done = false;
    if (!attr_done) {
        cudaFuncSetAttribute(flash_kernel,
                             cudaFuncAttributeMaxDynamicSharedMemorySize,
                             SMEM_FLASH_FLOATS * sizeof(float));
        cudaFuncSetAttribute(gemm_mma_kernel,
                             cudaFuncAttributeMaxDynamicSharedMemorySize,
                             GEMM_SMEM_DYN);
        attr_done = true;
    }

    // 0. bf16 splits of x, w_qkv, w_o
    split_kernel<<<(ML * DD / 4 + 255) / 256, 256>>>(x, xh, xl, ML * DD / 4);
    split_kernel<<<(3 * DD * DD / 4 + 255) / 256, 256>>>(w_qkv, wqh, wql, 3 * DD * DD / 4);
    split_kernel<<<(DD * DD / 4 + 255) / 256, 256>>>(w_o, woh, wol, DD * DD / 4);

    // 1. QKV projection (mma.sync): [4096,1024] @ [3072,1024]^T
    {
        dim3 grid(3 * DD / 128, ML / 128);
        gemm_mma_kernel<<<grid, 256, GEMM_SMEM_DYN>>>(xh, xl, wqh, wql, qkv_ptr,
                                                      ML, 3 * DD, DD);
    }
    // 2. RoPE + transpose
    {
        dim3 grid(LL / 64, BB * HH);
        rope_transpose_kernel<<<grid, 256>>>(cosT, sinT);
    }
    // 3. Flash attention (fp32)
    {
        dim3 grid(LL / 128, BB * HH);
        flash_kernel<<<grid, 256, SMEM_FLASH_FLOATS * sizeof(float)>>>();
    }
    // 4. split att, then output projection (mma.sync): [4096,1024] @ [1024,1024]^T
    split_kernel<<<(ML * DD / 4 + 255) / 256, 256>>>(att_ptr, ah, al, ML * DD / 4);
    {
        dim3 grid(DD / 128, ML / 128);
        gemm_mma_kernel<<<grid, 256, GEMM_SMEM_DYN>>>(ah, al, woh, wol, out,
                                                      ML, DD, DD);
    }
}

// round 8
// speedup vs baseline: 2.9775x; 1.6586x over previous
#include <cuda_runtime.h>
#include <cuda_bf16.h>
#include <math.h>
#include <cstdint>

#define BB 2
#define LL 2048
#define DD 1024
#define HH 16
#define DH 64
#define ML (BB*LL)          // 4096 rows

// ---------------------------------------------------------------------------
// Scratch (allocation-free rule: device globals)
// ---------------------------------------------------------------------------
__device__ float g_qkv[ML * 3 * DD];        // [b,l,3,h,dh] fp32 (QKV gemm out)

// bf16 flash operands (written by rope kernel)
__device__ __nv_bfloat16 g_qh[BB*HH*LL*DH], g_ql[BB*HH*LL*DH];   // [bh][l][d], pre-scaled 1/8
__device__ __nv_bfloat16 g_kh[BB*HH*LL*DH], g_kl[BB*HH*LL*DH];   // [bh][l][d]
__device__ __nv_bfloat16 g_vth[BB*HH*DH*LL], g_vtl[BB*HH*DH*LL]; // [bh][d][l]

// bf16 split operands for mma GEMMs
__device__ __nv_bfloat16 g_xh[ML * DD],      g_xl[ML * DD];
__device__ __nv_bfloat16 g_wqh[3 * DD * DD], g_wql[3 * DD * DD];
__device__ __nv_bfloat16 g_woh[DD * DD],     g_wol[DD * DD];
__device__ __nv_bfloat16 g_ah[ML * DD],      g_al[ML * DD];      // flash out hi/lo

// ---------------------------------------------------------------------------
// PTX helpers (sm_100-safe)
// ---------------------------------------------------------------------------
__device__ __forceinline__ uint32_t smem_u32(const void* p) {
    uint32_t a;
    asm("{ .reg .u64 t; cvta.to.shared.u64 t, %1; cvt.u32.u64 %0, t; }" : "=r"(a) : "l"(p));
    return a;
}
#define CP_ASYNC16(dst, src) \
    asm volatile("cp.async.cg.shared.global [%0], [%1], 16;" :: "r"(dst), "l"(src))
#define CP_COMMIT()  asm volatile("cp.async.commit_group;")
#define CP_WAIT0()   asm volatile("cp.async.wait_group 0;" ::: "memory")
#define CP_WAIT1()   asm volatile("cp.async.wait_group 1;" ::: "memory")

__device__ __forceinline__ void ldsm_x4(uint32_t* r, uint32_t addr) {
    asm volatile("ldmatrix.sync.aligned.m8n8.x4.shared.b16 {%0,%1,%2,%3}, [%4];"
                 : "=r"(r[0]), "=r"(r[1]), "=r"(r[2]), "=r"(r[3]) : "r"(addr));
}
__device__ __forceinline__ void mma_bf16(float* d, const uint32_t* a,
                                         uint32_t b0, uint32_t b1) {
    asm volatile(
        "mma.sync.aligned.m16n8k16.row.col.f32.bf16.bf16.f32 "
        "{%0,%1,%2,%3}, {%4,%5,%6,%7}, {%8,%9}, {%0,%1,%2,%3};"
        : "+f"(d[0]), "+f"(d[1]), "+f"(d[2]), "+f"(d[3])
        : "r"(a[0]), "r"(a[1]), "r"(a[2]), "r"(a[3]), "r"(b0), "r"(b1));
}

__device__ __forceinline__ void split1(float x, __nv_bfloat16& h, __nv_bfloat16& l) {
    h = __float2bfloat16_rn(x);
    l = __float2bfloat16_rn(x - __bfloat162float(h));
}
__device__ __forceinline__ uint32_t pack_bf16(float x, float y) {
    __nv_bfloat162 t;
    t.x = __float2bfloat16_rn(x);
    t.y = __float2bfloat16_rn(y);
    return *reinterpret_cast<uint32_t*>(&t);
}

// ---------------------------------------------------------------------------
// Split fp32 -> bf16 hi/lo
// ---------------------------------------------------------------------------
__global__ __launch_bounds__(256) void split_kernel(
    const float* __restrict__ src, __nv_bfloat16* __restrict__ hi,
    __nv_bfloat16* __restrict__ lo, int n4)
{
    int i = blockIdx.x * blockDim.x + threadIdx.x;
    if (i >= n4) return;
    float4 v = reinterpret_cast<const float4*>(src)[i];
    __nv_bfloat162 hh0, hh1, ll0, ll1;
    split1(v.x, hh0.x, ll0.x); split1(v.y, hh0.y, ll0.y);
    split1(v.z, hh1.x, ll1.x); split1(v.w, hh1.y, ll1.y);
    reinterpret_cast<__nv_bfloat162*>(hi)[i * 2]     = hh0;
    reinterpret_cast<__nv_bfloat162*>(hi)[i * 2 + 1] = hh1;
    reinterpret_cast<__nv_bfloat162*>(lo)[i * 2]     = ll0;
    reinterpret_cast<__nv_bfloat162*>(lo)[i * 2 + 1] = ll1;
}

// ---------------------------------------------------------------------------
// mma.sync GEMM: C[M,N] = A[M,K] @ W[N,K]^T via bf16x3.
// 128x128 CTA tile, 8 warps 2x4, K-chunk 32, double-buffered cp.async.
// ---------------------------------------------------------------------------
#define KC 32
#define ROWB 80
#define TILE_B (128 * ROWB)
#define BUF_B  (4 * TILE_B)
#define GEMM_SMEM_DYN (2 * BUF_B)

__global__ __launch_bounds__(256, 2) void gemm_mma_kernel(
    const __nv_bfloat16* __restrict__ Ah, const __nv_bfloat16* __restrict__ Al,
    const __nv_bfloat16* __restrict__ Wh, const __nv_bfloat16* __restrict__ Wl,
    float* __restrict__ C, int M, int N, int K)
{
    extern __shared__ uint8_t sm8[];
    const uint32_t sbase = smem_u32(sm8);

    const int tid  = threadIdx.x;
    const int wid  = tid >> 5;
    const int lane = tid & 31;
    const int m0 = blockIdx.y * 128;
    const int n0 = blockIdx.x * 128;
    const int wm = (wid & 1) * 64;
    const int wn = (wid >> 1) * 32;

    float acc[4][4][4];
#pragma unroll
    for (int i = 0; i < 4; i++)
#pragma unroll
        for (int j = 0; j < 4; j++)
#pragma unroll
            for (int q = 0; q < 4; q++) acc[i][j][q] = 0.f;

    const uint32_t aOff = (uint32_t)((wm + (lane & 15)) * ROWB + (lane >> 4) * 16);
    const uint32_t bOff = (uint32_t)((wn + (lane & 7) + ((lane >> 4) << 3)) * ROWB
                                     + ((lane >> 3) & 1) * 16);
    const int nc = K / KC;

    auto issue_loads = [&](int c, int buf) {
        const int kc = c * KC;
        const uint32_t dstb = sbase + buf * BUF_B;
#pragma unroll
        for (int it = 0; it < 8; it++) {
            int op = tid + it * 256;
            int t = op >> 9;
            int r = (op >> 2) & 127;
            int p = op & 3;
            const __nv_bfloat16* srcp;
            if (t == 0)      srcp = Ah + (size_t)(m0 + r) * K + kc + p * 8;
            else if (t == 1) srcp = Al + (size_t)(m0 + r) * K + kc + p * 8;
            else if (t == 2) srcp = Wh + (size_t)(n0 + r) * K + kc + p * 8;
            else             srcp = Wl + (size_t)(n0 + r) * K + kc + p * 8;
            CP_ASYNC16(dstb + t * TILE_B + r * ROWB + p * 16, srcp);
        }
        CP_COMMIT();
    };

    issue_loads(0, 0);

    for (int c = 0; c < nc; c++) {
        if (c + 1 < nc) { issue_loads(c + 1, (c + 1) & 1); CP_WAIT1(); }
        else            { CP_WAIT0(); }
        __syncthreads();

        const uint32_t dstb = sbase + (c & 1) * BUF_B;
#pragma unroll
        for (int pass = 0; pass < 3; pass++) {
            const uint32_t aBase = dstb + (pass == 2 ? TILE_B : 0);
            const uint32_t bBase = dstb + 2 * TILE_B + (pass == 1 ? TILE_B : 0);
#pragma unroll
            for (int step = 0; step < 2; step++) {
                uint32_t aF[4][4];
                uint32_t bF[8];
#pragma unroll
                for (int mt = 0; mt < 4; mt++)
                    ldsm_x4(aF[mt], aBase + aOff + mt * 16 * ROWB + step * 32);
#pragma unroll
                for (int nt2 = 0; nt2 < 2; nt2++)
                    ldsm_x4(bF + nt2 * 4, bBase + bOff + nt2 * 16 * ROWB + step * 32);
#pragma unroll
                for (int mt = 0; mt < 4; mt++)
#pragma unroll
                    for (int nt = 0; nt < 4; nt++) {
                        int bi = (nt >> 1) * 4 + (nt & 1) * 2;
                        mma_bf16(acc[mt][nt], aF[mt], bF[bi], bF[bi + 1]);
                    }
            }
        }
        __syncthreads();
    }

    const int rb = lane >> 2;
    const int cb = (lane & 3) * 2;
#pragma unroll
    for (int mt = 0; mt < 4; mt++)
#pragma unroll
        for (int nt = 0; nt < 4; nt++) {
            int row = m0 + wm + mt * 16 + rb;
            int col = n0 + wn + nt * 8 + cb;
            *reinterpret_cast<float2*>(&C[(size_t)row * N + col]) =
                make_float2(acc[mt][nt][0], acc[mt][nt][1]);
            *reinterpret_cast<float2*>(&C[(size_t)(row + 8) * N + col]) =
                make_float2(acc[mt][nt][2], acc[mt][nt][3]);
        }
}

// ---------------------------------------------------------------------------
// RoPE + split to bf16 hi/lo. Q pre-scaled by 0.125 (exact).
// q,k -> [bh][l][d]; v -> transposed [bh][d][l].
// ---------------------------------------------------------------------------
__global__ __launch_bounds__(256) void rope_split_kernel(
    const float* __restrict__ cosT, const float* __restrict__ sinT)
{
    __shared__ float Vs[64][65];

    const int tid = threadIdx.x;
    const int bh = blockIdx.y;
    const int b = bh >> 4;
    const int h = bh & 15;
    const int l0 = blockIdx.x * 64;

#pragma unroll
    for (int it = 0; it < 8; it++) {
        int p = tid + it * 256;
        int l = p >> 5;
        int i = p & 31;
        int lg = l0 + l;
        size_t base = ((size_t)(b * LL + lg) * 3) * DD + h * 64;
        float c0 = cosT[lg * 64 + i],      s0 = sinT[lg * 64 + i];
        float c1 = cosT[lg * 64 + i + 32], s1 = sinT[lg * 64 + i + 32];
        size_t qi = ((size_t)bh * LL + lg) * 64;

        float q1 = g_qkv[base + i], q2 = g_qkv[base + i + 32];
        float qa = (q1 * c0 - q2 * s0) * 0.125f;
        float qb = (q2 * c1 + q1 * s1) * 0.125f;
        __nv_bfloat16 hh, ll;
        split1(qa, hh, ll); g_qh[qi + i] = hh;      g_ql[qi + i] = ll;
        split1(qb, hh, ll); g_qh[qi + i + 32] = hh; g_ql[qi + i + 32] = ll;

        float k1 = g_qkv[base + DD + i], k2 = g_qkv[base + DD + i + 32];
        float ka = k1 * c0 - k2 * s0;
        float kb = k2 * c1 + k1 * s1;
        split1(ka, hh, ll); g_kh[qi + i] = hh;      g_kl[qi + i] = ll;
        split1(kb, hh, ll); g_kh[qi + i + 32] = hh; g_kl[qi + i + 32] = ll;
    }

    // V tile into smem (fp32), then transposed bf16 hi/lo write
#pragma unroll
    for (int it = 0; it < 4; it++) {
        int f = tid + it * 256;
        int r = f >> 4;
        int dq = (f & 15) * 4;
        float4 vv = *reinterpret_cast<const float4*>(
            &g_qkv[((size_t)(b * LL + l0 + r) * 3 + 2) * DD + h * 64 + dq]);
        Vs[r][dq] = vv.x; Vs[r][dq + 1] = vv.y; Vs[r][dq + 2] = vv.z; Vs[r][dq + 3] = vv.w;
    }
    __syncthreads();
#pragma unroll
    for (int it = 0; it < 4; it++) {
        int f = tid + it * 256;
        int d = f >> 4;
        int lq = (f & 15) * 4;
        size_t vi = ((size_t)(bh * 64 + d)) * LL + l0 + lq;
        __nv_bfloat162 h2a, h2b, l2a, l2b;
        split1(Vs[lq][d],     h2a.x, l2a.x); split1(Vs[lq + 1][d], h2a.y, l2a.y);
        split1(Vs[lq + 2][d], h2b.x, l2b.x); split1(Vs[lq + 3][d], h2b.y, l2b.y);
        *reinterpret_cast<__nv_bfloat162*>(&g_vth[vi])     = h2a;
        *reinterpret_cast<__nv_bfloat162*>(&g_vth[vi + 2]) = h2b;
        *reinterpret_cast<__nv_bfloat162*>(&g_vtl[vi])     = l2a;
        *reinterpret_cast<__nv_bfloat162*>(&g_vtl[vi + 2]) = l2b;
    }
}

// ---------------------------------------------------------------------------
// Flash attention with mma.sync bf16x3.
// CTA: 128 q rows x full KV (chunks of 64). 8 warps, each 16 q rows.
// Flash tiles have 64 bf16 = 128B data per row -> row stride FROWB=144
// (conflict-free: 144B = 36 words; 8 rows hit banks 0,4,...,28).
// smem: Qh/Ql [128][144], double-buffered Kh/Kl/Vth/Vtl [64][144].
// ---------------------------------------------------------------------------
#define FROWB 144
#define F_QTILE (128 * FROWB)             // 18432
#define F_KTILE (64 * FROWB)              // 9216
#define F_QH 0
#define F_QL F_QTILE
#define F_KV (2 * F_QTILE)                // 36864
#define F_KVSTRIDE (4 * F_KTILE)          // 36864 per buffer
#define FLASH_SMEM (F_KV + 2 * F_KVSTRIDE)  // 110592

__global__ __launch_bounds__(256) void flash_mma_kernel()
{
    extern __shared__ uint8_t sm8[];
    const uint32_t sbase = smem_u32(sm8);

    const int tid  = threadIdx.x;
    const int wid  = tid >> 5;
    const int lane = tid & 31;
    const int bh = blockIdx.y;
    const int b = bh >> 4;
    const int h = bh & 15;
    const int q0 = blockIdx.x * 128;
    const int wm = wid * 16;

    const __nv_bfloat16* qhp = g_qh + (size_t)bh * LL * 64;
    const __nv_bfloat16* qlp = g_ql + (size_t)bh * LL * 64;
    const __nv_bfloat16* khp = g_kh + (size_t)bh * LL * 64;
    const __nv_bfloat16* klp = g_kl + (size_t)bh * LL * 64;
    const __nv_bfloat16* vhp = g_vth + (size_t)bh * 64 * LL;
    const __nv_bfloat16* vlp = g_vtl + (size_t)bh * 64 * LL;

    const uint32_t aOff = (uint32_t)((wm + (lane & 15)) * FROWB + (lane >> 4) * 16);
    const uint32_t bOff = (uint32_t)(((lane & 7) + ((lane >> 4) << 3)) * FROWB
                                     + ((lane >> 3) & 1) * 16);

    // ---- prologue: Q tiles (2048 x 16B ops, 8/thread) ----
    {
#pragma unroll
        for (int it = 0; it < 8; it++) {
            int op = tid + it * 256;
            int t = op >> 10;            // 0=Qh 1=Ql
            int r = (op >> 3) & 127;
            int p = op & 7;
            const __nv_bfloat16* srcp = (t == 0 ? qhp : qlp) + (size_t)(q0 + r) * 64 + p * 8;
            CP_ASYNC16(sbase + t * F_QTILE + r * FROWB + p * 16, srcp);
        }
        CP_COMMIT();
    }

    auto issue_kv = [&](int c, int buf) {
        const int kt0 = c * 64;
        const uint32_t dstb = sbase + F_KV + buf * F_KVSTRIDE;
#pragma unroll
        for (int it = 0; it < 8; it++) {
            int op = tid + it * 256;
            int t = op >> 9;             // 0=Kh 1=Kl 2=Vh 3=Vl
            int r = (op >> 3) & 63;
            int p = op & 7;
            const __nv_bfloat16* srcp;
            if (t == 0)      srcp = khp + (size_t)(kt0 + r) * 64 + p * 8;
            else if (t == 1) srcp = klp + (size_t)(kt0 + r) * 64 + p * 8;
            else if (t == 2) srcp = vhp + (size_t)r * LL + kt0 + p * 8;
            else             srcp = vlp + (size_t)r * LL + kt0 + p * 8;
            CP_ASYNC16(dstb + t * F_KTILE + r * FROWB + p * 16, srcp);
        }
        CP_COMMIT();
    };

    issue_kv(0, 0);

    uint32_t qfh[4][4], qfl[4][4];
    float o[8][4];
    float m_lo = -INFINITY, m_hi = -INFINITY, l_lo = 0.f, l_hi = 0.f;
#pragma unroll
    for (int i = 0; i < 8; i++)
#pragma unroll
        for (int j = 0; j < 4; j++) o[i][j] = 0.f;

    const int NCHUNK = LL / 64;
    for (int c = 0; c < NCHUNK; c++) {
        if (c + 1 < NCHUNK) { issue_kv(c + 1, (c + 1) & 1); CP_WAIT1(); }
        else                { CP_WAIT0(); }
        __syncthreads();

        if (c == 0) {
#pragma unroll
            for (int st = 0; st < 4; st++) {
                ldsm_x4(qfh[st], sbase + F_QH + aOff + st * 32);
                ldsm_x4(qfl[st], sbase + F_QL + aOff + st * 32);
            }
        }

        const uint32_t kvb = sbase + F_KV + (c & 1) * F_KVSTRIDE;
        const uint32_t khB = kvb;
        const uint32_t klB = kvb + F_KTILE;
        const uint32_t vhB = kvb + 2 * F_KTILE;
        const uint32_t vlB = kvb + 3 * F_KTILE;

        // ---- S = Q K^T (3-pass) ----
        float sa[8][4];
#pragma unroll
        for (int i = 0; i < 8; i++)
#pragma unroll
            for (int j = 0; j < 4; j++) sa[i][j] = 0.f;

#pragma unroll
        for (int st = 0; st < 4; st++) {
#pragma unroll
            for (int nt2 = 0; nt2 < 4; nt2++) {
                uint32_t kh4[4], kl4[4];
                ldsm_x4(kh4, khB + bOff + nt2 * 16 * FROWB + st * 32);
                ldsm_x4(kl4, klB + bOff + nt2 * 16 * FROWB + st * 32);
#pragma unroll
                for (int hf = 0; hf < 2; hf++) {
                    int nt = nt2 * 2 + hf;
                    int bi = hf * 2;
                    mma_bf16(sa[nt], qfh[st], kh4[bi], kh4[bi + 1]);
                    mma_bf16(sa[nt], qfh[st], kl4[bi], kl4[bi + 1]);
                    mma_bf16(sa[nt], qfl[st], kh4[bi], kh4[bi + 1]);
                }
            }
        }

        // ---- online softmax (rows lo: lane/4, hi: +8) ----
        float mxlo = -INFINITY, mxhi = -INFINITY;
#pragma unroll
        for (int nt = 0; nt < 8; nt++) {
            mxlo = fmaxf(mxlo, fmaxf(sa[nt][0], sa[nt][1]));
            mxhi = fmaxf(mxhi, fmaxf(sa[nt][2], sa[nt][3]));
        }
        mxlo = fmaxf(mxlo, __shfl_xor_sync(0xffffffffu, mxlo, 1));
        mxlo = fmaxf(mxlo, __shfl_xor_sync(0xffffffffu, mxlo, 2));
        mxhi = fmaxf(mxhi, __shfl_xor_sync(0xffffffffu, mxhi, 1));
        mxhi = fmaxf(mxhi, __shfl_xor_sync(0xffffffffu, mxhi, 2));

        float mnlo = fmaxf(m_lo, mxlo), mnhi = fmaxf(m_hi, mxhi);
        float faclo = __expf(m_lo - mnlo), fachi = __expf(m_hi - mnhi);
        m_lo = mnlo; m_hi = mnhi;

        float rslo = 0.f, rshi = 0.f;
#pragma unroll
        for (int nt = 0; nt < 8; nt++) {
            sa[nt][0] = __expf(sa[nt][0] - mnlo);
            sa[nt][1] = __expf(sa[nt][1] - mnlo);
            sa[nt][2] = __expf(sa[nt][2] - mnhi);
            sa[nt][3] = __expf(sa[nt][3] - mnhi);
            rslo += sa[nt][0] + sa[nt][1];
            rshi += sa[nt][2] + sa[nt][3];
        }
        l_lo = l_lo * faclo + rslo;
        l_hi = l_hi * fachi + rshi;
#pragma unroll
        for (int nt = 0; nt < 8; nt++) {
            o[nt][0] *= faclo; o[nt][1] *= faclo;
            o[nt][2] *= fachi; o[nt][3] *= fachi;
        }

        // ---- P -> bf16 hi/lo A-fragments (register remap, no smem) ----
        uint32_t ph[4][4], pl[4][4];
#pragma unroll
        for (int t = 0; t < 4; t++) {
#pragma unroll
            for (int half = 0; half < 2; half++) {
                int nt = 2 * t + half;
#pragma unroll
                for (int rr = 0; rr < 2; rr++) {
                    float x = sa[nt][rr * 2], y = sa[nt][rr * 2 + 1];
                    uint32_t hp = pack_bf16(x, y);
                    __nv_bfloat162 hv = *reinterpret_cast<__nv_bfloat162*>(&hp);
                    uint32_t lp = pack_bf16(x - __bfloat162float(hv.x),
                                            y - __bfloat162float(hv.y));
                    ph[t][half * 2 + rr] = hp;
                    pl[t][half * 2 + rr] = lp;
                }
            }
        }

        // ---- O += P @ V (3-pass) ----
#pragma unroll
        for (int t = 0; t < 4; t++) {
#pragma unroll
            for (int nt2 = 0; nt2 < 4; nt2++) {
                uint32_t vh4[4], vl4[4];
                ldsm_x4(vh4, vhB + bOff + nt2 * 16 * FROWB + t * 32);
                ldsm_x4(vl4, vlB + bOff + nt2 * 16 * FROWB + t * 32);
#pragma unroll
                for (int hf = 0; hf < 2; hf++) {
                    int nt = nt2 * 2 + hf;
                    int bi = hf * 2;
                    mma_bf16(o[nt], ph[t], vh4[bi], vh4[bi + 1]);
                    mma_bf16(o[nt], ph[t], vl4[bi], vl4[bi + 1]);
                    mma_bf16(o[nt], pl[t], vh4[bi], vh4[bi + 1]);
                }
            }
        }
        __syncthreads();
    }

    // ---- epilogue: normalize, write bf16 hi/lo to g_ah/g_al ----
    l_lo += __shfl_xor_sync(0xffffffffu, l_lo, 1);
    l_lo += __shfl_xor_sync(0xffffffffu, l_lo, 2);
    l_hi += __shfl_xor_sync(0xffffffffu, l_hi, 1);
    l_hi += __shfl_xor_sync(0xffffffffu, l_hi, 2);
    float invlo = 1.f / l_lo, invhi = 1.f / l_hi;

    const int rlo = wm + (lane >> 2);
    const int cb = (lane & 3) * 2;
#pragma unroll
    for (int nt = 0; nt < 8; nt++) {
        {
            size_t idx = ((size_t)(b * LL + q0 + rlo)) * DD + h * 64 + nt * 8 + cb;
            float x = o[nt][0] * invlo, y = o[nt][1] * invlo;
            __nv_bfloat162 hv, lv;
            split1(x, hv.x, lv.x); split1(y, hv.y, lv.y);
            *reinterpret_cast<__nv_bfloat162*>(&g_ah[idx]) = hv;
            *reinterpret_cast<__nv_bfloat162*>(&g_al[idx]) = lv;
        }
        {
            size_t idx = ((size_t)(b * LL + q0 + rlo + 8)) * DD + h * 64 + nt * 8 + cb;
            float x = o[nt][2] * invhi, y = o[nt][3] * invhi;
            __nv_bfloat162 hv, lv;
            split1(x, hv.x, lv.x); split1(y, hv.y, lv.y);
            *reinterpret_cast<__nv_bfloat162*>(&g_ah[idx]) = hv;
            *reinterpret_cast<__nv_bfloat162*>(&g_al[idx]) = lv;
        }
    }
}

// ---------------------------------------------------------------------------
extern "C" void kernel_launch(void* const* d_in, const int* in_sizes, int n_in,
                              void* d_out, int out_size)
{
    const float* x     = (const float*)d_in[0];
    const float* cosT  = (const float*)d_in[1];
    const float* sinT  = (const float*)d_in[2];
    const float* w_qkv = (const float*)d_in[3];
    const float* w_o   = (const float*)d_in[4];
    float* out = (float*)d_out;

    float* qkv_ptr;
    __nv_bfloat16 *xh, *xl, *wqh, *wql, *woh, *wol, *ah, *al;
    cudaGetSymbolAddress((void**)&qkv_ptr, g_qkv);
    cudaGetSymbolAddress((void**)&xh, g_xh);   cudaGetSymbolAddress((void**)&xl, g_xl);
    cudaGetSymbolAddress((void**)&wqh, g_wqh); cudaGetSymbolAddress((void**)&wql, g_wql);
    cudaGetSymbolAddress((void**)&woh, g_woh); cudaGetSymbolAddress((void**)&wol, g_wol);
    cudaGetSymbolAddress((void**)&ah, g_ah);   cudaGetSymbolAddress((void**)&al, g_al);

    cudaFuncSetAttribute(gemm_mma_kernel,
                         cudaFuncAttributeMaxDynamicSharedMemorySize, GEMM_SMEM_DYN);
    cudaFuncSetAttribute(flash_mma_kernel,
                         cudaFuncAttributeMaxDynamicSharedMemorySize, FLASH_SMEM);

    // 0. bf16 splits of x, w_qkv, w_o
    split_kernel<<<(ML * DD / 4 + 255) / 256, 256>>>(x, xh, xl, ML * DD / 4);
    split_kernel<<<(3 * DD * DD / 4 + 255) / 256, 256>>>(w_qkv, wqh, wql, 3 * DD * DD / 4);
    split_kernel<<<(DD * DD / 4 + 255) / 256, 256>>>(w_o, woh, wol, DD * DD / 4);

    // 1. QKV projection (mma.sync): [4096,1024] @ [3072,1024]^T
    {
        dim3 grid(3 * DD / 128, ML / 128);
        gemm_mma_kernel<<<grid, 256, GEMM_SMEM_DYN>>>(xh, xl, wqh, wql, qkv_ptr,
                                                      ML, 3 * DD, DD);
    }
    // 2. RoPE + bf16 split (q scaled by 1/8) + V transpose
    {
        dim3 grid(LL / 64, BB * HH);
        rope_split_kernel<<<grid, 256>>>(cosT, sinT);
    }
    // 3. Flash attention (mma.sync bf16x3) -> writes g_ah/g_al directly
    {
        dim3 grid(LL / 128, BB * HH);
        flash_mma_kernel<<<grid, 256, FLASH_SMEM>>>();
    }
    // 4. Output projection (mma.sync): [4096,1024] @ [1024,1024]^T
    {
        dim3 grid(DD / 128, ML / 128);
        gemm_mma_kernel<<<grid, 256, GEMM_SMEM_DYN>>>(ah, al, woh, wol, out,
                                                      ML, DD, DD);
    }
}

// round 9
// speedup vs baseline: 3.1188x; 1.0475x over previous
#include <cuda_runtime.h>
#include <cuda_bf16.h>
#include <math.h>
#include <cstdint>

#define BB 2
#define LL 2048
#define DD 1024
#define HH 16
#define DH 64
#define ML (BB*LL)          // 4096 rows

// ---------------------------------------------------------------------------
// Scratch (allocation-free rule: device globals)
// ---------------------------------------------------------------------------
__device__ float g_qkv[ML * 3 * DD];        // [b,l,3,h,dh] fp32 (QKV gemm out)

// bf16 flash operands (written by rope kernel)
__device__ __nv_bfloat16 g_qh[BB*HH*LL*DH], g_ql[BB*HH*LL*DH];   // [bh][l][d], pre-scaled 1/8
__device__ __nv_bfloat16 g_kh[BB*HH*LL*DH], g_kl[BB*HH*LL*DH];   // [bh][l][d]
__device__ __nv_bfloat16 g_vth[BB*HH*DH*LL], g_vtl[BB*HH*DH*LL]; // [bh][d][l]

// bf16 split operands for mma GEMMs
__device__ __nv_bfloat16 g_xh[ML * DD],      g_xl[ML * DD];
__device__ __nv_bfloat16 g_wqh[3 * DD * DD], g_wql[3 * DD * DD];
__device__ __nv_bfloat16 g_woh[DD * DD],     g_wol[DD * DD];
__device__ __nv_bfloat16 g_ah[ML * DD],      g_al[ML * DD];      // flash out hi/lo

// ---------------------------------------------------------------------------
// PTX helpers (sm_100-safe)
// ---------------------------------------------------------------------------
__device__ __forceinline__ uint32_t smem_u32(const void* p) {
    uint32_t a;
    asm("{ .reg .u64 t; cvta.to.shared.u64 t, %1; cvt.u32.u64 %0, t; }" : "=r"(a) : "l"(p));
    return a;
}
#define CP_ASYNC16(dst, src) \
    asm volatile("cp.async.cg.shared.global [%0], [%1], 16;" :: "r"(dst), "l"(src))
#define CP_COMMIT()  asm volatile("cp.async.commit_group;")
#define CP_WAIT0()   asm volatile("cp.async.wait_group 0;" ::: "memory")
#define CP_WAIT1()   asm volatile("cp.async.wait_group 1;" ::: "memory")

__device__ __forceinline__ void ldsm_x4(uint32_t* r, uint32_t addr) {
    asm volatile("ldmatrix.sync.aligned.m8n8.x4.shared.b16 {%0,%1,%2,%3}, [%4];"
                 : "=r"(r[0]), "=r"(r[1]), "=r"(r[2]), "=r"(r[3]) : "r"(addr));
}
__device__ __forceinline__ void mma_bf16(float* d, const uint32_t* a,
                                         uint32_t b0, uint32_t b1) {
    asm volatile(
        "mma.sync.aligned.m16n8k16.row.col.f32.bf16.bf16.f32 "
        "{%0,%1,%2,%3}, {%4,%5,%6,%7}, {%8,%9}, {%0,%1,%2,%3};"
        : "+f"(d[0]), "+f"(d[1]), "+f"(d[2]), "+f"(d[3])
        : "r"(a[0]), "r"(a[1]), "r"(a[2]), "r"(a[3]), "r"(b0), "r"(b1));
}

__device__ __forceinline__ void split1(float x, __nv_bfloat16& h, __nv_bfloat16& l) {
    h = __float2bfloat16_rn(x);
    l = __float2bfloat16_rn(x - __bfloat162float(h));
}
__device__ __forceinline__ uint32_t pack_bf16(float x, float y) {
    __nv_bfloat162 t;
    t.x = __float2bfloat16_rn(x);
    t.y = __float2bfloat16_rn(y);
    return *reinterpret_cast<uint32_t*>(&t);
}

// ---------------------------------------------------------------------------
// Split fp32 -> bf16 hi/lo
// ---------------------------------------------------------------------------
__global__ __launch_bounds__(256) void split_kernel(
    const float* __restrict__ src, __nv_bfloat16* __restrict__ hi,
    __nv_bfloat16* __restrict__ lo, int n4)
{
    int i = blockIdx.x * blockDim.x + threadIdx.x;
    if (i >= n4) return;
    float4 v = reinterpret_cast<const float4*>(src)[i];
    __nv_bfloat162 hh0, hh1, ll0, ll1;
    split1(v.x, hh0.x, ll0.x); split1(v.y, hh0.y, ll0.y);
    split1(v.z, hh1.x, ll1.x); split1(v.w, hh1.y, ll1.y);
    reinterpret_cast<__nv_bfloat162*>(hi)[i * 2]     = hh0;
    reinterpret_cast<__nv_bfloat162*>(hi)[i * 2 + 1] = hh1;
    reinterpret_cast<__nv_bfloat162*>(lo)[i * 2]     = ll0;
    reinterpret_cast<__nv_bfloat162*>(lo)[i * 2 + 1] = ll1;
}

// ---------------------------------------------------------------------------
// mma.sync GEMM: C[M,N] = A[M,K] @ W[N,K]^T via bf16x3.
// 128x128 CTA tile, 8 warps 2x4, K-chunk 32, double-buffered cp.async.
// Fragment sharing: per step load Ah+Al once (8 ldsm), Wh group -> 32 mma,
// Wl group -> 16 mma. 12 ldsm / 48 mma per step (was 18).
// ---------------------------------------------------------------------------
#define KC 32
#define ROWB 80
#define TILE_B (128 * ROWB)
#define BUF_B  (4 * TILE_B)
#define GEMM_SMEM_DYN (2 * BUF_B)

__global__ __launch_bounds__(256, 2) void gemm_mma_kernel(
    const __nv_bfloat16* __restrict__ Ah, const __nv_bfloat16* __restrict__ Al,
    const __nv_bfloat16* __restrict__ Wh, const __nv_bfloat16* __restrict__ Wl,
    float* __restrict__ C, int M, int N, int K)
{
    extern __shared__ uint8_t sm8[];
    const uint32_t sbase = smem_u32(sm8);

    const int tid  = threadIdx.x;
    const int wid  = tid >> 5;
    const int lane = tid & 31;
    const int m0 = blockIdx.y * 128;
    const int n0 = blockIdx.x * 128;
    const int wm = (wid & 1) * 64;
    const int wn = (wid >> 1) * 32;

    float acc[4][4][4];
#pragma unroll
    for (int i = 0; i < 4; i++)
#pragma unroll
        for (int j = 0; j < 4; j++)
#pragma unroll
            for (int q = 0; q < 4; q++) acc[i][j][q] = 0.f;

    const uint32_t aOff = (uint32_t)((wm + (lane & 15)) * ROWB + (lane >> 4) * 16);
    const uint32_t bOff = (uint32_t)((wn + (lane & 7) + ((lane >> 4) << 3)) * ROWB
                                     + ((lane >> 3) & 1) * 16);
    const int nc = K / KC;

    auto issue_loads = [&](int c, int buf) {
        const int kc = c * KC;
        const uint32_t dstb = sbase + buf * BUF_B;
#pragma unroll
        for (int it = 0; it < 8; it++) {
            int op = tid + it * 256;
            int t = op >> 9;
            int r = (op >> 2) & 127;
            int p = op & 3;
            const __nv_bfloat16* srcp;
            if (t == 0)      srcp = Ah + (size_t)(m0 + r) * K + kc + p * 8;
            else if (t == 1) srcp = Al + (size_t)(m0 + r) * K + kc + p * 8;
            else if (t == 2) srcp = Wh + (size_t)(n0 + r) * K + kc + p * 8;
            else             srcp = Wl + (size_t)(n0 + r) * K + kc + p * 8;
            CP_ASYNC16(dstb + t * TILE_B + r * ROWB + p * 16, srcp);
        }
        CP_COMMIT();
    };

    issue_loads(0, 0);

    for (int c = 0; c < nc; c++) {
        if (c + 1 < nc) { issue_loads(c + 1, (c + 1) & 1); CP_WAIT1(); }
        else            { CP_WAIT0(); }
        __syncthreads();

        const uint32_t dstb = sbase + (c & 1) * BUF_B;
#pragma unroll
        for (int step = 0; step < 2; step++) {
            // load A fragments once for all passes
            uint32_t aFh[4][4], aFl[4][4];
#pragma unroll
            for (int mt = 0; mt < 4; mt++) {
                ldsm_x4(aFh[mt], dstb + aOff + mt * 16 * ROWB + step * 32);
                ldsm_x4(aFl[mt], dstb + TILE_B + aOff + mt * 16 * ROWB + step * 32);
            }
            // Wh group: AhWh + AlWh
            {
                uint32_t bF[8];
#pragma unroll
                for (int nt2 = 0; nt2 < 2; nt2++)
                    ldsm_x4(bF + nt2 * 4, dstb + 2 * TILE_B + bOff + nt2 * 16 * ROWB + step * 32);
#pragma unroll
                for (int mt = 0; mt < 4; mt++)
#pragma unroll
                    for (int nt = 0; nt < 4; nt++) {
                        int bi = (nt >> 1) * 4 + (nt & 1) * 2;
                        mma_bf16(acc[mt][nt], aFh[mt], bF[bi], bF[bi + 1]);
                        mma_bf16(acc[mt][nt], aFl[mt], bF[bi], bF[bi + 1]);
                    }
            }
            // Wl group: AhWl
            {
                uint32_t bF[8];
#pragma unroll
                for (int nt2 = 0; nt2 < 2; nt2++)
                    ldsm_x4(bF + nt2 * 4, dstb + 3 * TILE_B + bOff + nt2 * 16 * ROWB + step * 32);
#pragma unroll
                for (int mt = 0; mt < 4; mt++)
#pragma unroll
                    for (int nt = 0; nt < 4; nt++) {
                        int bi = (nt >> 1) * 4 + (nt & 1) * 2;
                        mma_bf16(acc[mt][nt], aFh[mt], bF[bi], bF[bi + 1]);
                    }
            }
        }
        __syncthreads();
    }

    const int rb = lane >> 2;
    const int cb = (lane & 3) * 2;
#pragma unroll
    for (int mt = 0; mt < 4; mt++)
#pragma unroll
        for (int nt = 0; nt < 4; nt++) {
            int row = m0 + wm + mt * 16 + rb;
            int col = n0 + wn + nt * 8 + cb;
            *reinterpret_cast<float2*>(&C[(size_t)row * N + col]) =
                make_float2(acc[mt][nt][0], acc[mt][nt][1]);
            *reinterpret_cast<float2*>(&C[(size_t)(row + 8) * N + col]) =
                make_float2(acc[mt][nt][2], acc[mt][nt][3]);
        }
}

// ---------------------------------------------------------------------------
// RoPE + split to bf16 hi/lo. Q pre-scaled by 0.125 (exact).
// q,k -> [bh][l][d]; v -> transposed [bh][d][l].
// ---------------------------------------------------------------------------
__global__ __launch_bounds__(256) void rope_split_kernel(
    const float* __restrict__ cosT, const float* __restrict__ sinT)
{
    __shared__ float Vs[64][65];

    const int tid = threadIdx.x;
    const int bh = blockIdx.y;
    const int b = bh >> 4;
    const int h = bh & 15;
    const int l0 = blockIdx.x * 64;

#pragma unroll
    for (int it = 0; it < 8; it++) {
        int p = tid + it * 256;
        int l = p >> 5;
        int i = p & 31;
        int lg = l0 + l;
        size_t base = ((size_t)(b * LL + lg) * 3) * DD + h * 64;
        float c0 = cosT[lg * 64 + i],      s0 = sinT[lg * 64 + i];
        float c1 = cosT[lg * 64 + i + 32], s1 = sinT[lg * 64 + i + 32];
        size_t qi = ((size_t)bh * LL + lg) * 64;

        float q1 = g_qkv[base + i], q2 = g_qkv[base + i + 32];
        float qa = (q1 * c0 - q2 * s0) * 0.125f;
        float qb = (q2 * c1 + q1 * s1) * 0.125f;
        __nv_bfloat16 hh, ll;
        split1(qa, hh, ll); g_qh[qi + i] = hh;      g_ql[qi + i] = ll;
        split1(qb, hh, ll); g_qh[qi + i + 32] = hh; g_ql[qi + i + 32] = ll;

        float k1 = g_qkv[base + DD + i], k2 = g_qkv[base + DD + i + 32];
        float ka = k1 * c0 - k2 * s0;
        float kb = k2 * c1 + k1 * s1;
        split1(ka, hh, ll); g_kh[qi + i] = hh;      g_kl[qi + i] = ll;
        split1(kb, hh, ll); g_kh[qi + i + 32] = hh; g_kl[qi + i + 32] = ll;
    }

    // V tile into smem (fp32), then transposed bf16 hi/lo write
#pragma unroll
    for (int it = 0; it < 4; it++) {
        int f = tid + it * 256;
        int r = f >> 4;
        int dq = (f & 15) * 4;
        float4 vv = *reinterpret_cast<const float4*>(
            &g_qkv[((size_t)(b * LL + l0 + r) * 3 + 2) * DD + h * 64 + dq]);
        Vs[r][dq] = vv.x; Vs[r][dq + 1] = vv.y; Vs[r][dq + 2] = vv.z; Vs[r][dq + 3] = vv.w;
    }
    __syncthreads();
#pragma unroll
    for (int it = 0; it < 4; it++) {
        int f = tid + it * 256;
        int d = f >> 4;
        int lq = (f & 15) * 4;
        size_t vi = ((size_t)(bh * 64 + d)) * LL + l0 + lq;
        __nv_bfloat162 h2a, h2b, l2a, l2b;
        split1(Vs[lq][d],     h2a.x, l2a.x); split1(Vs[lq + 1][d], h2a.y, l2a.y);
        split1(Vs[lq + 2][d], h2b.x, l2b.x); split1(Vs[lq + 3][d], h2b.y, l2b.y);
        *reinterpret_cast<__nv_bfloat162*>(&g_vth[vi])     = h2a;
        *reinterpret_cast<__nv_bfloat162*>(&g_vth[vi + 2]) = h2b;
        *reinterpret_cast<__nv_bfloat162*>(&g_vtl[vi])     = l2a;
        *reinterpret_cast<__nv_bfloat162*>(&g_vtl[vi + 2]) = l2b;
    }
}

// ---------------------------------------------------------------------------
// Flash attention with mma.sync bf16x3. 2 CTA/SM target (regs capped 128;
// 2 x 110592B smem = 216KB fits the 228KB SM).
// ---------------------------------------------------------------------------
#define FROWB 144
#define F_QTILE (128 * FROWB)             // 18432
#define F_KTILE (64 * FROWB)              // 9216
#define F_QH 0
#define F_QL F_QTILE
#define F_KV (2 * F_QTILE)                // 36864
#define F_KVSTRIDE (4 * F_KTILE)          // 36864 per buffer
#define FLASH_SMEM (F_KV + 2 * F_KVSTRIDE)  // 110592

__global__ __launch_bounds__(256, 2) void flash_mma_kernel()
{
    extern __shared__ uint8_t sm8[];
    const uint32_t sbase = smem_u32(sm8);

    const int tid  = threadIdx.x;
    const int wid  = tid >> 5;
    const int lane = tid & 31;
    const int bh = blockIdx.y;
    const int b = bh >> 4;
    const int h = bh & 15;
    const int q0 = blockIdx.x * 128;
    const int wm = wid * 16;

    const __nv_bfloat16* qhp = g_qh + (size_t)bh * LL * 64;
    const __nv_bfloat16* qlp = g_ql + (size_t)bh * LL * 64;
    const __nv_bfloat16* khp = g_kh + (size_t)bh * LL * 64;
    const __nv_bfloat16* klp = g_kl + (size_t)bh * LL * 64;
    const __nv_bfloat16* vhp = g_vth + (size_t)bh * 64 * LL;
    const __nv_bfloat16* vlp = g_vtl + (size_t)bh * 64 * LL;

    const uint32_t aOff = (uint32_t)((wm + (lane & 15)) * FROWB + (lane >> 4) * 16);
    const uint32_t bOff = (uint32_t)(((lane & 7) + ((lane >> 4) << 3)) * FROWB
                                     + ((lane >> 3) & 1) * 16);

    // ---- prologue: Q tiles ----
    {
#pragma unroll
        for (int it = 0; it < 8; it++) {
            int op = tid + it * 256;
            int t = op >> 10;            // 0=Qh 1=Ql
            int r = (op >> 3) & 127;
            int p = op & 7;
            const __nv_bfloat16* srcp = (t == 0 ? qhp : qlp) + (size_t)(q0 + r) * 64 + p * 8;
            CP_ASYNC16(sbase + t * F_QTILE + r * FROWB + p * 16, srcp);
        }
        CP_COMMIT();
    }

    auto issue_kv = [&](int c, int buf) {
        const int kt0 = c * 64;
        const uint32_t dstb = sbase + F_KV + buf * F_KVSTRIDE;
#pragma unroll
        for (int it = 0; it < 8; it++) {
            int op = tid + it * 256;
            int t = op >> 9;             // 0=Kh 1=Kl 2=Vh 3=Vl
            int r = (op >> 3) & 63;
            int p = op & 7;
            const __nv_bfloat16* srcp;
            if (t == 0)      srcp = khp + (size_t)(kt0 + r) * 64 + p * 8;
            else if (t == 1) srcp = klp + (size_t)(kt0 + r) * 64 + p * 8;
            else if (t == 2) srcp = vhp + (size_t)r * LL + kt0 + p * 8;
            else             srcp = vlp + (size_t)r * LL + kt0 + p * 8;
            CP_ASYNC16(dstb + t * F_KTILE + r * FROWB + p * 16, srcp);
        }
        CP_COMMIT();
    };

    issue_kv(0, 0);

    uint32_t qfh[4][4], qfl[4][4];
    float o[8][4];
    float m_lo = -INFINITY, m_hi = -INFINITY, l_lo = 0.f, l_hi = 0.f;
#pragma unroll
    for (int i = 0; i < 8; i++)
#pragma unroll
        for (int j = 0; j < 4; j++) o[i][j] = 0.f;

    const int NCHUNK = LL / 64;
    for (int c = 0; c < NCHUNK; c++) {
        if (c + 1 < NCHUNK) { issue_kv(c + 1, (c + 1) & 1); CP_WAIT1(); }
        else                { CP_WAIT0(); }
        __syncthreads();

        if (c == 0) {
#pragma unroll
            for (int st = 0; st < 4; st++) {
                ldsm_x4(qfh[st], sbase + F_QH + aOff + st * 32);
                ldsm_x4(qfl[st], sbase + F_QL + aOff + st * 32);
            }
        }

        const uint32_t kvb = sbase + F_KV + (c & 1) * F_KVSTRIDE;
        const uint32_t khB = kvb;
        const uint32_t klB = kvb + F_KTILE;
        const uint32_t vhB = kvb + 2 * F_KTILE;
        const uint32_t vlB = kvb + 3 * F_KTILE;

        // ---- S = Q K^T (3-pass) ----
        float sa[8][4];
#pragma unroll
        for (int i = 0; i < 8; i++)
#pragma unroll
            for (int j = 0; j < 4; j++) sa[i][j] = 0.f;

#pragma unroll
        for (int st = 0; st < 4; st++) {
#pragma unroll
            for (int nt2 = 0; nt2 < 4; nt2++) {
                uint32_t kh4[4], kl4[4];
                ldsm_x4(kh4, khB + bOff + nt2 * 16 * FROWB + st * 32);
                ldsm_x4(kl4, klB + bOff + nt2 * 16 * FROWB + st * 32);
#pragma unroll
                for (int hf = 0; hf < 2; hf++) {
                    int nt = nt2 * 2 + hf;
                    int bi = hf * 2;
                    mma_bf16(sa[nt], qfh[st], kh4[bi], kh4[bi + 1]);
                    mma_bf16(sa[nt], qfh[st], kl4[bi], kl4[bi + 1]);
                    mma_bf16(sa[nt], qfl[st], kh4[bi], kh4[bi + 1]);
                }
            }
        }

        // ---- online softmax (rows lo: lane/4, hi: +8) ----
        float mxlo = -INFINITY, mxhi = -INFINITY;
#pragma unroll
        for (int nt = 0; nt < 8; nt++) {
            mxlo = fmaxf(mxlo, fmaxf(sa[nt][0], sa[nt][1]));
            mxhi = fmaxf(mxhi, fmaxf(sa[nt][2], sa[nt][3]));
        }
        mxlo = fmaxf(mxlo, __shfl_xor_sync(0xffffffffu, mxlo, 1));
        mxlo = fmaxf(mxlo, __shfl_xor_sync(0xffffffffu, mxlo, 2));
        mxhi = fmaxf(mxhi, __shfl_xor_sync(0xffffffffu, mxhi, 1));
        mxhi = fmaxf(mxhi, __shfl_xor_sync(0xffffffffu, mxhi, 2));

        float mnlo = fmaxf(m_lo, mxlo), mnhi = fmaxf(m_hi, mxhi);
        float faclo = __expf(m_lo - mnlo), fachi = __expf(m_hi - mnhi);
        m_lo = mnlo; m_hi = mnhi;

        float rslo = 0.f, rshi = 0.f;
#pragma unroll
        for (int nt = 0; nt < 8; nt++) {
            sa[nt][0] = __expf(sa[nt][0] - mnlo);
            sa[nt][1] = __expf(sa[nt][1] - mnlo);
            sa[nt][2] = __expf(sa[nt][2] - mnhi);
            sa[nt][3] = __expf(sa[nt][3] - mnhi);
            rslo += sa[nt][0] + sa[nt][1];
            rshi += sa[nt][2] + sa[nt][3];
        }
        l_lo = l_lo * faclo + rslo;
        l_hi = l_hi * fachi + rshi;
#pragma unroll
        for (int nt = 0; nt < 8; nt++) {
            o[nt][0] *= faclo; o[nt][1] *= faclo;
            o[nt][2] *= fachi; o[nt][3] *= fachi;
        }

        // ---- P -> bf16 hi/lo A-fragments (register remap, no smem) ----
        uint32_t ph[4][4], pl[4][4];
#pragma unroll
        for (int t = 0; t < 4; t++) {
#pragma unroll
            for (int half = 0; half < 2; half++) {
                int nt = 2 * t + half;
#pragma unroll
                for (int rr = 0; rr < 2; rr++) {
                    float x = sa[nt][rr * 2], y = sa[nt][rr * 2 + 1];
                    uint32_t hp = pack_bf16(x, y);
                    __nv_bfloat162 hv = *reinterpret_cast<__nv_bfloat162*>(&hp);
                    uint32_t lp = pack_bf16(x - __bfloat162float(hv.x),
                                            y - __bfloat162float(hv.y));
                    ph[t][half * 2 + rr] = hp;
                    pl[t][half * 2 + rr] = lp;
                }
            }
        }

        // ---- O += P @ V (3-pass) ----
#pragma unroll
        for (int t = 0; t < 4; t++) {
#pragma unroll
            for (int nt2 = 0; nt2 < 4; nt2++) {
                uint32_t vh4[4], vl4[4];
                ldsm_x4(vh4, vhB + bOff + nt2 * 16 * FROWB + t * 32);
                ldsm_x4(vl4, vlB + bOff + nt2 * 16 * FROWB + t * 32);
#pragma unroll
                for (int hf = 0; hf < 2; hf++) {
                    int nt = nt2 * 2 + hf;
                    int bi = hf * 2;
                    mma_bf16(o[nt], ph[t], vh4[bi], vh4[bi + 1]);
                    mma_bf16(o[nt], ph[t], vl4[bi], vl4[bi + 1]);
                    mma_bf16(o[nt], pl[t], vh4[bi], vh4[bi + 1]);
                }
            }
        }
        __syncthreads();
    }

    // ---- epilogue: normalize, write bf16 hi/lo to g_ah/g_al ----
    l_lo += __shfl_xor_sync(0xffffffffu, l_lo, 1);
    l_lo += __shfl_xor_sync(0xffffffffu, l_lo, 2);
    l_hi += __shfl_xor_sync(0xffffffffu, l_hi, 1);
    l_hi += __shfl_xor_sync(0xffffffffu, l_hi, 2);
    float invlo = 1.f / l_lo, invhi = 1.f / l_hi;

    const int rlo = wm + (lane >> 2);
    const int cb = (lane & 3) * 2;
#pragma unroll
    for (int nt = 0; nt < 8; nt++) {
        {
            size_t idx = ((size_t)(b * LL + q0 + rlo)) * DD + h * 64 + nt * 8 + cb;
            float x = o[nt][0] * invlo, y = o[nt][1] * invlo;
            __nv_bfloat162 hv, lv;
            split1(x, hv.x, lv.x); split1(y, hv.y, lv.y);
            *reinterpret_cast<__nv_bfloat162*>(&g_ah[idx]) = hv;
            *reinterpret_cast<__nv_bfloat162*>(&g_al[idx]) = lv;
        }
        {
            size_t idx = ((size_t)(b * LL + q0 + rlo + 8)) * DD + h * 64 + nt * 8 + cb;
            float x = o[nt][2] * invhi, y = o[nt][3] * invhi;
            __nv_bfloat162 hv, lv;
            split1(x, hv.x, lv.x); split1(y, hv.y, lv.y);
            *reinterpret_cast<__nv_bfloat162*>(&g_ah[idx]) = hv;
            *reinterpret_cast<__nv_bfloat162*>(&g_al[idx]) = lv;
        }
    }
}

// ---------------------------------------------------------------------------
extern "C" void kernel_launch(void* const* d_in, const int* in_sizes, int n_in,
                              void* d_out, int out_size)
{
    const float* x     = (const float*)d_in[0];
    const float* cosT  = (const float*)d_in[1];
    const float* sinT  = (const float*)d_in[2];
    const float* w_qkv = (const float*)d_in[3];
    const float* w_o   = (const float*)d_in[4];
    float* out = (float*)d_out;

    float* qkv_ptr;
    __nv_bfloat16 *xh, *xl, *wqh, *wql, *woh, *wol, *ah, *al;
    cudaGetSymbolAddress((void**)&qkv_ptr, g_qkv);
    cudaGetSymbolAddress((void**)&xh, g_xh);   cudaGetSymbolAddress((void**)&xl, g_xl);
    cudaGetSymbolAddress((void**)&wqh, g_wqh); cudaGetSymbolAddress((void**)&wql, g_wql);
    cudaGetSymbolAddress((void**)&woh, g_woh); cudaGetSymbolAddress((void**)&wol, g_wol);
    cudaGetSymbolAddress((void**)&ah, g_ah);   cudaGetSymbolAddress((void**)&al, g_al);

    cudaFuncSetAttribute(gemm_mma_kernel,
                         cudaFuncAttributeMaxDynamicSharedMemorySize, GEMM_SMEM_DYN);
    cudaFuncSetAttribute(flash_mma_kernel,
                         cudaFuncAttributeMaxDynamicSharedMemorySize, FLASH_SMEM);

    // 0. bf16 splits of x, w_qkv, w_o
    split_kernel<<<(ML * DD / 4 + 255) / 256, 256>>>(x, xh, xl, ML * DD / 4);
    split_kernel<<<(3 * DD * DD / 4 + 255) / 256, 256>>>(w_qkv, wqh, wql, 3 * DD * DD / 4);
    split_kernel<<<(DD * DD / 4 + 255) / 256, 256>>>(w_o, woh, wol, DD * DD / 4);

    // 1. QKV projection (mma.sync): [4096,1024] @ [3072,1024]^T
    {
        dim3 grid(3 * DD / 128, ML / 128);
        gemm_mma_kernel<<<grid, 256, GEMM_SMEM_DYN>>>(xh, xl, wqh, wql, qkv_ptr,
                                                      ML, 3 * DD, DD);
    }
    // 2. RoPE + bf16 split (q scaled by 1/8) + V transpose
    {
        dim3 grid(LL / 64, BB * HH);
        rope_split_kernel<<<grid, 256>>>(cosT, sinT);
    }
    // 3. Flash attention (mma.sync bf16x3) -> writes g_ah/g_al directly
    {
        dim3 grid(LL / 128, BB * HH);
        flash_mma_kernel<<<grid, 256, FLASH_SMEM>>>();
    }
    // 4. Output projection (mma.sync): [4096,1024] @ [1024,1024]^T
    {
        dim3 grid(DD / 128, ML / 128);
        gemm_mma_kernel<<<grid, 256, GEMM_SMEM_DYN>>>(ah, al, woh, wol, out,
                                                      ML, DD, DD);
    }
}

// round 10
// speedup vs baseline: 3.1632x; 1.0142x over previous
#include <cuda_runtime.h>
#include <cuda_bf16.h>
#include <math.h>
#include <cstdint>

#define BB 2
#define LL 2048
#define DD 1024
#define HH 16
#define DH 64
#define ML (BB*LL)          // 4096 rows

// ---------------------------------------------------------------------------
// Scratch (allocation-free rule: device globals)
// ---------------------------------------------------------------------------
__device__ float g_qkv[ML * 3 * DD];        // [b,l,3,h,dh] fp32 (QKV gemm out)

// bf16 flash operands (written by rope kernel)
__device__ __nv_bfloat16 g_qh[BB*HH*LL*DH], g_ql[BB*HH*LL*DH];   // [bh][l][d], pre-scaled 1/8
__device__ __nv_bfloat16 g_kh[BB*HH*LL*DH], g_kl[BB*HH*LL*DH];   // [bh][l][d]
__device__ __nv_bfloat16 g_vth[BB*HH*DH*LL], g_vtl[BB*HH*DH*LL]; // [bh][d][l]

// bf16 split operands for mma GEMMs
__device__ __nv_bfloat16 g_xh[ML * DD],      g_xl[ML * DD];
__device__ __nv_bfloat16 g_wqh[3 * DD * DD], g_wql[3 * DD * DD];
__device__ __nv_bfloat16 g_woh[DD * DD],     g_wol[DD * DD];
__device__ __nv_bfloat16 g_ah[ML * DD],      g_al[ML * DD];      // flash out hi/lo

// ---------------------------------------------------------------------------
// PTX helpers (sm_100-safe)
// ---------------------------------------------------------------------------
__device__ __forceinline__ uint32_t smem_u32(const void* p) {
    uint32_t a;
    asm("{ .reg .u64 t; cvta.to.shared.u64 t, %1; cvt.u32.u64 %0, t; }" : "=r"(a) : "l"(p));
    return a;
}
#define CP_ASYNC16(dst, src) \
    asm volatile("cp.async.cg.shared.global [%0], [%1], 16;" :: "r"(dst), "l"(src))
#define CP_COMMIT()  asm volatile("cp.async.commit_group;")
#define CP_WAIT0()   asm volatile("cp.async.wait_group 0;" ::: "memory")
#define CP_WAIT1()   asm volatile("cp.async.wait_group 1;" ::: "memory")

__device__ __forceinline__ void ldsm_x4(uint32_t* r, uint32_t addr) {
    asm volatile("ldmatrix.sync.aligned.m8n8.x4.shared.b16 {%0,%1,%2,%3}, [%4];"
                 : "=r"(r[0]), "=r"(r[1]), "=r"(r[2]), "=r"(r[3]) : "r"(addr));
}
__device__ __forceinline__ void mma_bf16(float* d, const uint32_t* a,
                                         uint32_t b0, uint32_t b1) {
    asm volatile(
        "mma.sync.aligned.m16n8k16.row.col.f32.bf16.bf16.f32 "
        "{%0,%1,%2,%3}, {%4,%5,%6,%7}, {%8,%9}, {%0,%1,%2,%3};"
        : "+f"(d[0]), "+f"(d[1]), "+f"(d[2]), "+f"(d[3])
        : "r"(a[0]), "r"(a[1]), "r"(a[2]), "r"(a[3]), "r"(b0), "r"(b1));
}

__device__ __forceinline__ void split1(float x, __nv_bfloat16& h, __nv_bfloat16& l) {
    h = __float2bfloat16_rn(x);
    l = __float2bfloat16_rn(x - __bfloat162float(h));
}
__device__ __forceinline__ uint32_t pack_bf16(float x, float y) {
    __nv_bfloat162 t;
    t.x = __float2bfloat16_rn(x);
    t.y = __float2bfloat16_rn(y);
    return *reinterpret_cast<uint32_t*>(&t);
}

// ---------------------------------------------------------------------------
// Split fp32 -> bf16 hi/lo
// ---------------------------------------------------------------------------
__global__ __launch_bounds__(256) void split_kernel(
    const float* __restrict__ src, __nv_bfloat16* __restrict__ hi,
    __nv_bfloat16* __restrict__ lo, int n4)
{
    int i = blockIdx.x * blockDim.x + threadIdx.x;
    if (i >= n4) return;
    float4 v = reinterpret_cast<const float4*>(src)[i];
    __nv_bfloat162 hh0, hh1, ll0, ll1;
    split1(v.x, hh0.x, ll0.x); split1(v.y, hh0.y, ll0.y);
    split1(v.z, hh1.x, ll1.x); split1(v.w, hh1.y, ll1.y);
    reinterpret_cast<__nv_bfloat162*>(hi)[i * 2]     = hh0;
    reinterpret_cast<__nv_bfloat162*>(hi)[i * 2 + 1] = hh1;
    reinterpret_cast<__nv_bfloat162*>(lo)[i * 2]     = ll0;
    reinterpret_cast<__nv_bfloat162*>(lo)[i * 2 + 1] = ll1;
}

// ---------------------------------------------------------------------------
// mma.sync GEMM: C[M,N] = A[M,K] @ W[N,K]^T via bf16x3.
// Dependency-free mma scheduling: 3 groups of 16 independent mma per step.
// ---------------------------------------------------------------------------
#define KC 32
#define ROWB 80
#define TILE_B (128 * ROWB)
#define BUF_B  (4 * TILE_B)
#define GEMM_SMEM_DYN (2 * BUF_B)

__global__ __launch_bounds__(256, 2) void gemm_mma_kernel(
    const __nv_bfloat16* __restrict__ Ah, const __nv_bfloat16* __restrict__ Al,
    const __nv_bfloat16* __restrict__ Wh, const __nv_bfloat16* __restrict__ Wl,
    float* __restrict__ C, int M, int N, int K)
{
    extern __shared__ uint8_t sm8[];
    const uint32_t sbase = smem_u32(sm8);

    const int tid  = threadIdx.x;
    const int wid  = tid >> 5;
    const int lane = tid & 31;
    const int m0 = blockIdx.y * 128;
    const int n0 = blockIdx.x * 128;
    const int wm = (wid & 1) * 64;
    const int wn = (wid >> 1) * 32;

    float acc[4][4][4];
#pragma unroll
    for (int i = 0; i < 4; i++)
#pragma unroll
        for (int j = 0; j < 4; j++)
#pragma unroll
            for (int q = 0; q < 4; q++) acc[i][j][q] = 0.f;

    const uint32_t aOff = (uint32_t)((wm + (lane & 15)) * ROWB + (lane >> 4) * 16);
    const uint32_t bOff = (uint32_t)((wn + (lane & 7) + ((lane >> 4) << 3)) * ROWB
                                     + ((lane >> 3) & 1) * 16);
    const int nc = K / KC;

    auto issue_loads = [&](int c, int buf) {
        const int kc = c * KC;
        const uint32_t dstb = sbase + buf * BUF_B;
#pragma unroll
        for (int it = 0; it < 8; it++) {
            int op = tid + it * 256;
            int t = op >> 9;
            int r = (op >> 2) & 127;
            int p = op & 3;
            const __nv_bfloat16* srcp;
            if (t == 0)      srcp = Ah + (size_t)(m0 + r) * K + kc + p * 8;
            else if (t == 1) srcp = Al + (size_t)(m0 + r) * K + kc + p * 8;
            else if (t == 2) srcp = Wh + (size_t)(n0 + r) * K + kc + p * 8;
            else             srcp = Wl + (size_t)(n0 + r) * K + kc + p * 8;
            CP_ASYNC16(dstb + t * TILE_B + r * ROWB + p * 16, srcp);
        }
        CP_COMMIT();
    };

    issue_loads(0, 0);

    for (int c = 0; c < nc; c++) {
        if (c + 1 < nc) { issue_loads(c + 1, (c + 1) & 1); CP_WAIT1(); }
        else            { CP_WAIT0(); }
        __syncthreads();

        const uint32_t dstb = sbase + (c & 1) * BUF_B;
#pragma unroll
        for (int step = 0; step < 2; step++) {
            uint32_t aFh[4][4], aFl[4][4];
#pragma unroll
            for (int mt = 0; mt < 4; mt++) {
                ldsm_x4(aFh[mt], dstb + aOff + mt * 16 * ROWB + step * 32);
                ldsm_x4(aFl[mt], dstb + TILE_B + aOff + mt * 16 * ROWB + step * 32);
            }
            uint32_t bFh[8], bFl[8];
#pragma unroll
            for (int nt2 = 0; nt2 < 2; nt2++) {
                ldsm_x4(bFh + nt2 * 4, dstb + 2 * TILE_B + bOff + nt2 * 16 * ROWB + step * 32);
                ldsm_x4(bFl + nt2 * 4, dstb + 3 * TILE_B + bOff + nt2 * 16 * ROWB + step * 32);
            }
            // group 1: AhWh — 16 independent accs
#pragma unroll
            for (int mt = 0; mt < 4; mt++)
#pragma unroll
                for (int nt = 0; nt < 4; nt++) {
                    int bi = (nt >> 1) * 4 + (nt & 1) * 2;
                    mma_bf16(acc[mt][nt], aFh[mt], bFh[bi], bFh[bi + 1]);
                }
            // group 2: AlWh
#pragma unroll
            for (int mt = 0; mt < 4; mt++)
#pragma unroll
                for (int nt = 0; nt < 4; nt++) {
                    int bi = (nt >> 1) * 4 + (nt & 1) * 2;
                    mma_bf16(acc[mt][nt], aFl[mt], bFh[bi], bFh[bi + 1]);
                }
            // group 3: AhWl
#pragma unroll
            for (int mt = 0; mt < 4; mt++)
#pragma unroll
                for (int nt = 0; nt < 4; nt++) {
                    int bi = (nt >> 1) * 4 + (nt & 1) * 2;
                    mma_bf16(acc[mt][nt], aFh[mt], bFl[bi], bFl[bi + 1]);
                }
        }
        __syncthreads();
    }

    const int rb = lane >> 2;
    const int cb = (lane & 3) * 2;
#pragma unroll
    for (int mt = 0; mt < 4; mt++)
#pragma unroll
        for (int nt = 0; nt < 4; nt++) {
            int row = m0 + wm + mt * 16 + rb;
            int col = n0 + wn + nt * 8 + cb;
            *reinterpret_cast<float2*>(&C[(size_t)row * N + col]) =
                make_float2(acc[mt][nt][0], acc[mt][nt][1]);
            *reinterpret_cast<float2*>(&C[(size_t)(row + 8) * N + col]) =
                make_float2(acc[mt][nt][2], acc[mt][nt][3]);
        }
}

// ---------------------------------------------------------------------------
// RoPE + split to bf16 hi/lo. Q pre-scaled by 0.125 (exact).
// ---------------------------------------------------------------------------
__global__ __launch_bounds__(256) void rope_split_kernel(
    const float* __restrict__ cosT, const float* __restrict__ sinT)
{
    __shared__ float Vs[64][65];

    const int tid = threadIdx.x;
    const int bh = blockIdx.y;
    const int b = bh >> 4;
    const int h = bh & 15;
    const int l0 = blockIdx.x * 64;

#pragma unroll
    for (int it = 0; it < 8; it++) {
        int p = tid + it * 256;
        int l = p >> 5;
        int i = p & 31;
        int lg = l0 + l;
        size_t base = ((size_t)(b * LL + lg) * 3) * DD + h * 64;
        float c0 = cosT[lg * 64 + i],      s0 = sinT[lg * 64 + i];
        float c1 = cosT[lg * 64 + i + 32], s1 = sinT[lg * 64 + i + 32];
        size_t qi = ((size_t)bh * LL + lg) * 64;

        float q1 = g_qkv[base + i], q2 = g_qkv[base + i + 32];
        float qa = (q1 * c0 - q2 * s0) * 0.125f;
        float qb = (q2 * c1 + q1 * s1) * 0.125f;
        __nv_bfloat16 hh, ll;
        split1(qa, hh, ll); g_qh[qi + i] = hh;      g_ql[qi + i] = ll;
        split1(qb, hh, ll); g_qh[qi + i + 32] = hh; g_ql[qi + i + 32] = ll;

        float k1 = g_qkv[base + DD + i], k2 = g_qkv[base + DD + i + 32];
        float ka = k1 * c0 - k2 * s0;
        float kb = k2 * c1 + k1 * s1;
        split1(ka, hh, ll); g_kh[qi + i] = hh;      g_kl[qi + i] = ll;
        split1(kb, hh, ll); g_kh[qi + i + 32] = hh; g_kl[qi + i + 32] = ll;
    }

#pragma unroll
    for (int it = 0; it < 4; it++) {
        int f = tid + it * 256;
        int r = f >> 4;
        int dq = (f & 15) * 4;
        float4 vv = *reinterpret_cast<const float4*>(
            &g_qkv[((size_t)(b * LL + l0 + r) * 3 + 2) * DD + h * 64 + dq]);
        Vs[r][dq] = vv.x; Vs[r][dq + 1] = vv.y; Vs[r][dq + 2] = vv.z; Vs[r][dq + 3] = vv.w;
    }
    __syncthreads();
#pragma unroll
    for (int it = 0; it < 4; it++) {
        int f = tid + it * 256;
        int d = f >> 4;
        int lq = (f & 15) * 4;
        size_t vi = ((size_t)(bh * 64 + d)) * LL + l0 + lq;
        __nv_bfloat162 h2a, h2b, l2a, l2b;
        split1(Vs[lq][d],     h2a.x, l2a.x); split1(Vs[lq + 1][d], h2a.y, l2a.y);
        split1(Vs[lq + 2][d], h2b.x, l2b.x); split1(Vs[lq + 3][d], h2b.y, l2b.y);
        *reinterpret_cast<__nv_bfloat162*>(&g_vth[vi])     = h2a;
        *reinterpret_cast<__nv_bfloat162*>(&g_vth[vi + 2]) = h2b;
        *reinterpret_cast<__nv_bfloat162*>(&g_vtl[vi])     = l2a;
        *reinterpret_cast<__nv_bfloat162*>(&g_vtl[vi + 2]) = l2b;
    }
}

// ---------------------------------------------------------------------------
// Flash attention with mma.sync bf16x3, dependency-free mma groups.
// ---------------------------------------------------------------------------
#define FROWB 144
#define F_QTILE (128 * FROWB)             // 18432
#define F_KTILE (64 * FROWB)              // 9216
#define F_QH 0
#define F_QL F_QTILE
#define F_KV (2 * F_QTILE)                // 36864
#define F_KVSTRIDE (4 * F_KTILE)          // 36864 per buffer
#define FLASH_SMEM (F_KV + 2 * F_KVSTRIDE)  // 110592

__global__ __launch_bounds__(256, 2) void flash_mma_kernel()
{
    extern __shared__ uint8_t sm8[];
    const uint32_t sbase = smem_u32(sm8);

    const int tid  = threadIdx.x;
    const int wid  = tid >> 5;
    const int lane = tid & 31;
    const int bh = blockIdx.y;
    const int b = bh >> 4;
    const int h = bh & 15;
    const int q0 = blockIdx.x * 128;
    const int wm = wid * 16;

    const __nv_bfloat16* qhp = g_qh + (size_t)bh * LL * 64;
    const __nv_bfloat16* qlp = g_ql + (size_t)bh * LL * 64;
    const __nv_bfloat16* khp = g_kh + (size_t)bh * LL * 64;
    const __nv_bfloat16* klp = g_kl + (size_t)bh * LL * 64;
    const __nv_bfloat16* vhp = g_vth + (size_t)bh * 64 * LL;
    const __nv_bfloat16* vlp = g_vtl + (size_t)bh * 64 * LL;

    const uint32_t aOff = (uint32_t)((wm + (lane & 15)) * FROWB + (lane >> 4) * 16);
    const uint32_t bOff = (uint32_t)(((lane & 7) + ((lane >> 4) << 3)) * FROWB
                                     + ((lane >> 3) & 1) * 16);

    // ---- prologue: Q tiles ----
    {
#pragma unroll
        for (int it = 0; it < 8; it++) {
            int op = tid + it * 256;
            int t = op >> 10;            // 0=Qh 1=Ql
            int r = (op >> 3) & 127;
            int p = op & 7;
            const __nv_bfloat16* srcp = (t == 0 ? qhp : qlp) + (size_t)(q0 + r) * 64 + p * 8;
            CP_ASYNC16(sbase + t * F_QTILE + r * FROWB + p * 16, srcp);
        }
        CP_COMMIT();
    }

    auto issue_kv = [&](int c, int buf) {
        const int kt0 = c * 64;
        const uint32_t dstb = sbase + F_KV + buf * F_KVSTRIDE;
#pragma unroll
        for (int it = 0; it < 8; it++) {
            int op = tid + it * 256;
            int t = op >> 9;             // 0=Kh 1=Kl 2=Vh 3=Vl
            int r = (op >> 3) & 63;
            int p = op & 7;
            const __nv_bfloat16* srcp;
            if (t == 0)      srcp = khp + (size_t)(kt0 + r) * 64 + p * 8;
            else if (t == 1) srcp = klp + (size_t)(kt0 + r) * 64 + p * 8;
            else if (t == 2) srcp = vhp + (size_t)r * LL + kt0 + p * 8;
            else             srcp = vlp + (size_t)r * LL + kt0 + p * 8;
            CP_ASYNC16(dstb + t * F_KTILE + r * FROWB + p * 16, srcp);
        }
        CP_COMMIT();
    };

    issue_kv(0, 0);

    uint32_t qfh[4][4], qfl[4][4];
    float o[8][4];
    float m_lo = -INFINITY, m_hi = -INFINITY, l_lo = 0.f, l_hi = 0.f;
#pragma unroll
    for (int i = 0; i < 8; i++)
#pragma unroll
        for (int j = 0; j < 4; j++) o[i][j] = 0.f;

    const int NCHUNK = LL / 64;
    for (int c = 0; c < NCHUNK; c++) {
        if (c + 1 < NCHUNK) { issue_kv(c + 1, (c + 1) & 1); CP_WAIT1(); }
        else                { CP_WAIT0(); }
        __syncthreads();

        if (c == 0) {
#pragma unroll
            for (int st = 0; st < 4; st++) {
                ldsm_x4(qfh[st], sbase + F_QH + aOff + st * 32);
                ldsm_x4(qfl[st], sbase + F_QL + aOff + st * 32);
            }
        }

        const uint32_t kvb = sbase + F_KV + (c & 1) * F_KVSTRIDE;
        const uint32_t khB = kvb;
        const uint32_t klB = kvb + F_KTILE;
        const uint32_t vhB = kvb + 2 * F_KTILE;
        const uint32_t vlB = kvb + 3 * F_KTILE;

        // ---- S = Q K^T (3-pass, independent-acc groups of 4) ----
        float sa[8][4];
#pragma unroll
        for (int i = 0; i < 8; i++)
#pragma unroll
            for (int j = 0; j < 4; j++) sa[i][j] = 0.f;

#pragma unroll
        for (int st = 0; st < 4; st++) {
#pragma unroll
            for (int half = 0; half < 2; half++) {
                uint32_t kh4[2][4], kl4[2][4];
#pragma unroll
                for (int j = 0; j < 2; j++) {
                    int nt2 = half * 2 + j;
                    ldsm_x4(kh4[j], khB + bOff + nt2 * 16 * FROWB + st * 32);
                    ldsm_x4(kl4[j], klB + bOff + nt2 * 16 * FROWB + st * 32);
                }
                // group 1: qfh x kh — 4 independent accs
#pragma unroll
                for (int j = 0; j < 2; j++)
#pragma unroll
                    for (int hf = 0; hf < 2; hf++) {
                        int nt = (half * 2 + j) * 2 + hf;
                        mma_bf16(sa[nt], qfh[st], kh4[j][hf * 2], kh4[j][hf * 2 + 1]);
                    }
                // group 2: qfh x kl
#pragma unroll
                for (int j = 0; j < 2; j++)
#pragma unroll
                    for (int hf = 0; hf < 2; hf++) {
                        int nt = (half * 2 + j) * 2 + hf;
                        mma_bf16(sa[nt], qfh[st], kl4[j][hf * 2], kl4[j][hf * 2 + 1]);
                    }
                // group 3: qfl x kh
#pragma unroll
                for (int j = 0; j < 2; j++)
#pragma unroll
                    for (int hf = 0; hf < 2; hf++) {
                        int nt = (half * 2 + j) * 2 + hf;
                        mma_bf16(sa[nt], qfl[st], kh4[j][hf * 2], kh4[j][hf * 2 + 1]);
                    }
            }
        }

        // ---- online softmax (rows lo: lane/4, hi: +8) ----
        float mxlo = -INFINITY, mxhi = -INFINITY;
#pragma unroll
        for (int nt = 0; nt < 8; nt++) {
            mxlo = fmaxf(mxlo, fmaxf(sa[nt][0], sa[nt][1]));
            mxhi = fmaxf(mxhi, fmaxf(sa[nt][2], sa[nt][3]));
        }
        mxlo = fmaxf(mxlo, __shfl_xor_sync(0xffffffffu, mxlo, 1));
        mxlo = fmaxf(mxlo, __shfl_xor_sync(0xffffffffu, mxlo, 2));
        mxhi = fmaxf(mxhi, __shfl_xor_sync(0xffffffffu, mxhi, 1));
        mxhi = fmaxf(mxhi, __shfl_xor_sync(0xffffffffu, mxhi, 2));

        float mnlo = fmaxf(m_lo, mxlo), mnhi = fmaxf(m_hi, mxhi);
        float faclo = __expf(m_lo - mnlo), fachi = __expf(m_hi - mnhi);
        m_lo = mnlo; m_hi = mnhi;

        float rslo = 0.f, rshi = 0.f;
#pragma unroll
        for (int nt = 0; nt < 8; nt++) {
            sa[nt][0] = __expf(sa[nt][0] - mnlo);
            sa[nt][1] = __expf(sa[nt][1] - mnlo);
            sa[nt][2] = __expf(sa[nt][2] - mnhi);
            sa[nt][3] = __expf(sa[nt][3] - mnhi);
            rslo += sa[nt][0] + sa[nt][1];
            rshi += sa[nt][2] + sa[nt][3];
        }
        l_lo = l_lo * faclo + rslo;
        l_hi = l_hi * fachi + rshi;
#pragma unroll
        for (int nt = 0; nt < 8; nt++) {
            o[nt][0] *= faclo; o[nt][1] *= faclo;
            o[nt][2] *= fachi; o[nt][3] *= fachi;
        }

        // ---- P -> bf16 hi/lo A-fragments (register remap, no smem) ----
        uint32_t ph[4][4], pl[4][4];
#pragma unroll
        for (int t = 0; t < 4; t++) {
#pragma unroll
            for (int half = 0; half < 2; half++) {
                int nt = 2 * t + half;
#pragma unroll
                for (int rr = 0; rr < 2; rr++) {
                    float x = sa[nt][rr * 2], y = sa[nt][rr * 2 + 1];
                    uint32_t hp = pack_bf16(x, y);
                    __nv_bfloat162 hv = *reinterpret_cast<__nv_bfloat162*>(&hp);
                    uint32_t lp = pack_bf16(x - __bfloat162float(hv.x),
                                            y - __bfloat162float(hv.y));
                    ph[t][half * 2 + rr] = hp;
                    pl[t][half * 2 + rr] = lp;
                }
            }
        }

        // ---- O += P @ V (3-pass, independent-acc groups of 4) ----
#pragma unroll
        for (int t = 0; t < 4; t++) {
#pragma unroll
            for (int half = 0; half < 2; half++) {
                uint32_t vh4[2][4], vl4[2][4];
#pragma unroll
                for (int j = 0; j < 2; j++) {
                    int nt2 = half * 2 + j;
                    ldsm_x4(vh4[j], vhB + bOff + nt2 * 16 * FROWB + t * 32);
                    ldsm_x4(vl4[j], vlB + bOff + nt2 * 16 * FROWB + t * 32);
                }
                // group 1: ph x vh
#pragma unroll
                for (int j = 0; j < 2; j++)
#pragma unroll
                    for (int hf = 0; hf < 2; hf++) {
                        int nt = (half * 2 + j) * 2 + hf;
                        mma_bf16(o[nt], ph[t], vh4[j][hf * 2], vh4[j][hf * 2 + 1]);
                    }
                // group 2: ph x vl
#pragma unroll
                for (int j = 0; j < 2; j++)
#pragma unroll
                    for (int hf = 0; hf < 2; hf++) {
                        int nt = (half * 2 + j) * 2 + hf;
                        mma_bf16(o[nt], ph[t], vl4[j][hf * 2], vl4[j][hf * 2 + 1]);
                    }
                // group 3: pl x vh
#pragma unroll
                for (int j = 0; j < 2; j++)
#pragma unroll
                    for (int hf = 0; hf < 2; hf++) {
                        int nt = (half * 2 + j) * 2 + hf;
                        mma_bf16(o[nt], pl[t], vh4[j][hf * 2], vh4[j][hf * 2 + 1]);
                    }
            }
        }
        __syncthreads();
    }

    // ---- epilogue: normalize, write bf16 hi/lo to g_ah/g_al ----
    l_lo += __shfl_xor_sync(0xffffffffu, l_lo, 1);
    l_lo += __shfl_xor_sync(0xffffffffu, l_lo, 2);
    l_hi += __shfl_xor_sync(0xffffffffu, l_hi, 1);
    l_hi += __shfl_xor_sync(0xffffffffu, l_hi, 2);
    float invlo = 1.f / l_lo, invhi = 1.f / l_hi;

    const int rlo = wm + (lane >> 2);
    const int cb = (lane & 3) * 2;
#pragma unroll
    for (int nt = 0; nt < 8; nt++) {
        {
            size_t idx = ((size_t)(b * LL + q0 + rlo)) * DD + h * 64 + nt * 8 + cb;
            float x = o[nt][0] * invlo, y = o[nt][1] * invlo;
            __nv_bfloat162 hv, lv;
            split1(x, hv.x, lv.x); split1(y, hv.y, lv.y);
            *reinterpret_cast<__nv_bfloat162*>(&g_ah[idx]) = hv;
            *reinterpret_cast<__nv_bfloat162*>(&g_al[idx]) = lv;
        }
        {
            size_t idx = ((size_t)(b * LL + q0 + rlo + 8)) * DD + h * 64 + nt * 8 + cb;
            float x = o[nt][2] * invhi, y = o[nt][3] * invhi;
            __nv_bfloat162 hv, lv;
            split1(x, hv.x, lv.x); split1(y, hv.y, lv.y);
            *reinterpret_cast<__nv_bfloat162*>(&g_ah[idx]) = hv;
            *reinterpret_cast<__nv_bfloat162*>(&g_al[idx]) = lv;
        }
    }
}

// ---------------------------------------------------------------------------
extern "C" void kernel_launch(void* const* d_in, const int* in_sizes, int n_in,
                              void* d_out, int out_size)
{
    const float* x     = (const float*)d_in[0];
    const float* cosT  = (const float*)d_in[1];
    const float* sinT  = (const float*)d_in[2];
    const float* w_qkv = (const float*)d_in[3];
    const float* w_o   = (const float*)d_in[4];
    float* out = (float*)d_out;

    float* qkv_ptr;
    __nv_bfloat16 *xh, *xl, *wqh, *wql, *woh, *wol, *ah, *al;
    cudaGetSymbolAddress((void**)&qkv_ptr, g_qkv);
    cudaGetSymbolAddress((void**)&xh, g_xh);   cudaGetSymbolAddress((void**)&xl, g_xl);
    cudaGetSymbolAddress((void**)&wqh, g_wqh); cudaGetSymbolAddress((void**)&wql, g_wql);
    cudaGetSymbolAddress((void**)&woh, g_woh); cudaGetSymbolAddress((void**)&wol, g_wol);
    cudaGetSymbolAddress((void**)&ah, g_ah);   cudaGetSymbolAddress((void**)&al, g_al);

    cudaFuncSetAttribute(gemm_mma_kernel,
                         cudaFuncAttributeMaxDynamicSharedMemorySize, GEMM_SMEM_DYN);
    cudaFuncSetAttribute(flash_mma_kernel,
                         cudaFuncAttributeMaxDynamicSharedMemorySize, FLASH_SMEM);

    // 0. bf16 splits of x, w_qkv, w_o
    split_kernel<<<(ML * DD / 4 + 255) / 256, 256>>>(x, xh, xl, ML * DD / 4);
    split_kernel<<<(3 * DD * DD / 4 + 255) / 256, 256>>>(w_qkv, wqh, wql, 3 * DD * DD / 4);
    split_kernel<<<(DD * DD / 4 + 255) / 256, 256>>>(w_o, woh, wol, DD * DD / 4);

    // 1. QKV projection (mma.sync): [4096,1024] @ [3072,1024]^T
    {
        dim3 grid(3 * DD / 128, ML / 128);
        gemm_mma_kernel<<<grid, 256, GEMM_SMEM_DYN>>>(xh, xl, wqh, wql, qkv_ptr,
                                                      ML, 3 * DD, DD);
    }
    // 2. RoPE + bf16 split (q scaled by 1/8) + V transpose
    {
        dim3 grid(LL / 64, BB * HH);
        rope_split_kernel<<<grid, 256>>>(cosT, sinT);
    }
    // 3. Flash attention (mma.sync bf16x3) -> writes g_ah/g_al directly
    {
        dim3 grid(LL / 128, BB * HH);
        flash_mma_kernel<<<grid, 256, FLASH_SMEM>>>();
    }
    // 4. Output projection (mma.sync): [4096,1024] @ [1024,1024]^T
    {
        dim3 grid(DD / 128, ML / 128);
        gemm_mma_kernel<<<grid, 256, GEMM_SMEM_DYN>>>(ah, al, woh, wol, out,
                                                      ML, DD, DD);
    }
}